// round 9
// baseline (speedup 1.0000x reference)
#include <cuda_runtime.h>

// ---------------------------------------------------------------------------
// KMeanReservoir: nearest-centroid assignment.
//   sim[n,k] = 2*x[n].c[k] - |x[n]|^2 - |c[k]|^2
//   out[0:N)   = max_k sim[n,k]           (float32)
//   out[N:2N)  = argmax_k sim[n,k]        (as float32)
//
// Shapes: x [131072, 256] f32, centroids [1024, 256] f32.
// Strategy: implicit GEMM with running max/argmax; fp32 via packed
// fma.rn.f32x2 (FFMA2) for 2x the scalar-FFMA rate on sm_103a.
// ---------------------------------------------------------------------------

typedef unsigned long long u64;

__device__ __forceinline__ u64 pack2(float lo, float hi) {
    u64 r;
    asm("mov.b64 %0, {%1, %2};" : "=l"(r) : "f"(lo), "f"(hi));
    return r;
}
__device__ __forceinline__ u64 ffma2(u64 a, u64 b, u64 c) {
    u64 d;
    asm("fma.rn.f32x2 %0, %1, %2, %3;" : "=l"(d) : "l"(a), "l"(b), "l"(c));
    return d;
}
__device__ __forceinline__ void unpack2(u64 v, float& lo, float& hi) {
    asm("mov.b64 {%0, %1}, %2;" : "=f"(lo), "=f"(hi) : "l"(v));
}

// Scratch (allocation-free: __device__ globals)
__device__ float g_cnorm[1024];
__device__ float g_xnorm[131072];

// ---------------------------------------------------------------------------
// Row-norm kernels: one warp per 256-float row.
// ---------------------------------------------------------------------------
__global__ void xnorm_kernel(const float* __restrict__ src, int rows) {
    int warp = (blockIdx.x * blockDim.x + threadIdx.x) >> 5;
    int lane = threadIdx.x & 31;
    if (warp >= rows) return;
    const float4* r = (const float4*)(src + (size_t)warp * 256);
    float4 a = r[lane];
    float4 b = r[lane + 32];
    float s = a.x * a.x + a.y * a.y + a.z * a.z + a.w * a.w +
              b.x * b.x + b.y * b.y + b.z * b.z + b.w * b.w;
#pragma unroll
    for (int o = 16; o; o >>= 1) s += __shfl_xor_sync(0xffffffffu, s, o);
    if (lane == 0) g_xnorm[warp] = s;
}

__global__ void cnorm_kernel(const float* __restrict__ src, int rows) {
    int warp = (blockIdx.x * blockDim.x + threadIdx.x) >> 5;
    int lane = threadIdx.x & 31;
    if (warp >= rows) return;
    const float4* r = (const float4*)(src + (size_t)warp * 256);
    float4 a = r[lane];
    float4 b = r[lane + 32];
    float s = a.x * a.x + a.y * a.y + a.z * a.z + a.w * a.w +
              b.x * b.x + b.y * b.y + b.z * b.z + b.w * b.w;
#pragma unroll
    for (int o = 16; o; o >>= 1) s += __shfl_xor_sync(0xffffffffu, s, o);
    if (lane == 0) g_cnorm[warp] = s;
}

// ---------------------------------------------------------------------------
// Main kernel.
//   Block: 256 threads (tx = tid&15, ty = tid>>4), BM=128 rows, BN=128 cents.
//   Per thread: TM=8 rows (ty*8..+7), TN=8 cols STRIDED (tx + 16*i).
//   D chunked by 16, double-buffered smem, d-major tiles xs[d][m], cs[d][n].
//   Accumulators: row-paired f32x2 (4 pairs x 8 cols = 32 u64).
// ---------------------------------------------------------------------------
__global__ __launch_bounds__(256) void assign_kernel(
    const float* __restrict__ x, const float* __restrict__ c,
    float* __restrict__ out, int Ntot) {
    __shared__ __align__(16) float xs[2][16 * 128];
    __shared__ __align__(16) float cs[2][16 * 128];

    const int tid = threadIdx.x;
    const int tx = tid & 15;
    const int ty = tid >> 4;
    const int rowBase = blockIdx.x * 128;

    // Staging-load mapping: thread covers float4 indices 2*tid, 2*tid+1 over
    // (m in 0..127) x (u in 0..3), i.e. 2048 floats = one 16x128 chunk.
    const int i0 = tid * 2, i1 = tid * 2 + 1;
    const int m0 = i0 >> 2, u0 = i0 & 3;
    const int m1 = i1 >> 2, u1 = i1 & 3;

    const float* xp0 = x + (size_t)(rowBase + m0) * 256 + u0 * 4;
    const float* xp1 = x + (size_t)(rowBase + m1) * 256 + u1 * 4;

    u64 acc[4][8];
    float bestv[8];
    int besti[8];
#pragma unroll
    for (int p = 0; p < 8; p++) { bestv[p] = -3.4e38f; besti[p] = 0; }

    float4 X0, X1, C0, C1;
    int buf = 0;

    for (int kt = 0; kt < 8; ++kt) {
        const int cBase = kt * 128;
        const float* cp0 = c + (size_t)(cBase + m0) * 256 + u0 * 4;
        const float* cp1 = c + (size_t)(cBase + m1) * 256 + u1 * 4;

#pragma unroll
        for (int p = 0; p < 4; p++)
#pragma unroll
            for (int i = 0; i < 8; i++) acc[p][i] = 0ull;

        float cn[8];
#pragma unroll
        for (int i = 0; i < 8; i++) cn[i] = g_cnorm[cBase + tx + 16 * i];

        // ---- load chunk dc = 0 ----
        X0 = *(const float4*)(xp0);
        X1 = *(const float4*)(xp1);
        C0 = *(const float4*)(cp0);
        C1 = *(const float4*)(cp1);
        {
            float* xd = xs[buf];
            xd[(u0 * 4 + 0) * 128 + m0] = X0.x; xd[(u0 * 4 + 1) * 128 + m0] = X0.y;
            xd[(u0 * 4 + 2) * 128 + m0] = X0.z; xd[(u0 * 4 + 3) * 128 + m0] = X0.w;
            xd[(u1 * 4 + 0) * 128 + m1] = X1.x; xd[(u1 * 4 + 1) * 128 + m1] = X1.y;
            xd[(u1 * 4 + 2) * 128 + m1] = X1.z; xd[(u1 * 4 + 3) * 128 + m1] = X1.w;
            float* cd = cs[buf];
            cd[(u0 * 4 + 0) * 128 + m0] = C0.x; cd[(u0 * 4 + 1) * 128 + m0] = C0.y;
            cd[(u0 * 4 + 2) * 128 + m0] = C0.z; cd[(u0 * 4 + 3) * 128 + m0] = C0.w;
            cd[(u1 * 4 + 0) * 128 + m1] = C1.x; cd[(u1 * 4 + 1) * 128 + m1] = C1.y;
            cd[(u1 * 4 + 2) * 128 + m1] = C1.z; cd[(u1 * 4 + 3) * 128 + m1] = C1.w;
        }
        __syncthreads();

        for (int dc = 0; dc < 16; ++dc) {
            // ---- issue next chunk's global loads (latency hidden by compute)
            if (dc < 15) {
                const int dcb = (dc + 1) * 16;
                X0 = *(const float4*)(xp0 + dcb);
                X1 = *(const float4*)(xp1 + dcb);
                C0 = *(const float4*)(cp0 + dcb);
                C1 = *(const float4*)(cp1 + dcb);
            }

            // ---- compute current chunk ----
            const float* xbuf = xs[buf];
            const float* cbuf = cs[buf];
#pragma unroll
            for (int kk = 0; kk < 16; ++kk) {
                const float* xrow = xbuf + kk * 128 + ty * 8;
                // A: two 16B loads = 4 row-pairs (broadcast, conflict-free)
                ulonglong2 A0 = *(const ulonglong2*)(xrow);
                ulonglong2 A1 = *(const ulonglong2*)(xrow + 4);
                // B: 8 strided scalar loads (conflict-free: banks = tx+16i)
                const float* crow = cbuf + kk * 128 + tx;
                u64 bd[8];
#pragma unroll
                for (int i = 0; i < 8; i++) {
                    float b = crow[16 * i];
                    bd[i] = pack2(b, b);
                }
                u64 ap0 = A0.x, ap1 = A0.y, ap2 = A1.x, ap3 = A1.y;
#pragma unroll
                for (int i = 0; i < 8; i++) {
                    acc[0][i] = ffma2(ap0, bd[i], acc[0][i]);
                    acc[1][i] = ffma2(ap1, bd[i], acc[1][i]);
                    acc[2][i] = ffma2(ap2, bd[i], acc[2][i]);
                    acc[3][i] = ffma2(ap3, bd[i], acc[3][i]);
                }
            }

            // ---- store staged next chunk into the other buffer ----
            if (dc < 15) {
                int nb = buf ^ 1;
                float* xd = xs[nb];
                xd[(u0 * 4 + 0) * 128 + m0] = X0.x; xd[(u0 * 4 + 1) * 128 + m0] = X0.y;
                xd[(u0 * 4 + 2) * 128 + m0] = X0.z; xd[(u0 * 4 + 3) * 128 + m0] = X0.w;
                xd[(u1 * 4 + 0) * 128 + m1] = X1.x; xd[(u1 * 4 + 1) * 128 + m1] = X1.y;
                xd[(u1 * 4 + 2) * 128 + m1] = X1.z; xd[(u1 * 4 + 3) * 128 + m1] = X1.w;
                float* cd = cs[nb];
                cd[(u0 * 4 + 0) * 128 + m0] = C0.x; cd[(u0 * 4 + 1) * 128 + m0] = C0.y;
                cd[(u0 * 4 + 2) * 128 + m0] = C0.z; cd[(u0 * 4 + 3) * 128 + m0] = C0.w;
                cd[(u1 * 4 + 0) * 128 + m1] = C1.x; cd[(u1 * 4 + 1) * 128 + m1] = C1.y;
                cd[(u1 * 4 + 2) * 128 + m1] = C1.z; cd[(u1 * 4 + 3) * 128 + m1] = C1.w;
            }
            __syncthreads();
            buf ^= 1;
        }

        // ---- K-tile epilogue: sim = 2*acc - |c|^2, update running argmax ----
#pragma unroll
        for (int p = 0; p < 4; p++) {
#pragma unroll
            for (int i = 0; i < 8; i++) {
                float lo, hi;
                unpack2(acc[p][i], lo, hi);
                int n = cBase + tx + 16 * i;
                float v0 = 2.0f * lo - cn[i];
                float v1 = 2.0f * hi - cn[i];
                if (v0 > bestv[2 * p])     { bestv[2 * p] = v0;     besti[2 * p] = n; }
                if (v1 > bestv[2 * p + 1]) { bestv[2 * p + 1] = v1; besti[2 * p + 1] = n; }
            }
        }
    }

    // ---- cross-thread (tx) reduction via reused smem ----
    __syncthreads();
    float* redv = &xs[0][0];    // 2048 floats needed, 4096 available
    int* redi = (int*)&cs[0][0];
#pragma unroll
    for (int p = 0; p < 8; p++) {
        int row = ty * 8 + p;
        redv[row * 16 + tx] = bestv[p];
        redi[row * 16 + tx] = besti[p];
    }
    __syncthreads();
    if (tid < 128) {
        int row = tid;
        float bv = redv[row * 16];
        int bi = redi[row * 16];
#pragma unroll
        for (int j = 1; j < 16; j++) {
            float v = redv[row * 16 + j];
            int id = redi[row * 16 + j];
            if (v > bv || (v == bv && id < bi)) { bv = v; bi = id; }
        }
        int g = rowBase + row;
        out[g] = bv - g_xnorm[g];          // max_sim
        out[Ntot + g] = (float)bi;         // label as float
    }
}

// ---------------------------------------------------------------------------
extern "C" void kernel_launch(void* const* d_in, const int* in_sizes, int n_in,
                              void* d_out, int out_size) {
    const float* x = (const float*)d_in[0];
    const float* c = (const float*)d_in[1];
    float* out = (float*)d_out;

    const int D = 256;
    const int N = in_sizes[0] / D;   // 131072
    const int K = in_sizes[1] / D;   // 1024

    // Norms (one warp per row; 8 rows per 256-thread block)
    cnorm_kernel<<<(K + 7) / 8, 256>>>(c, K);
    xnorm_kernel<<<(N + 7) / 8, 256>>>(x, N);

    // Main assignment: BM=128 rows per block
    assign_kernel<<<N / 128, 256>>>(x, c, out, N);
}

// round 10
// speedup vs baseline: 1.0001x; 1.0001x over previous
#include <cuda_runtime.h>

// ---------------------------------------------------------------------------
// KMeanReservoir: nearest-centroid assignment.
//   sim[n,k] = 2*x[n].c[k] - |x[n]|^2 - |c[k]|^2
//   out[0:N)   = max_k sim[n,k]           (float32)
//   out[N:2N)  = argmax_k sim[n,k]        (as float32)
//
// Shapes: x [131072, 256] f32, centroids [1024, 256] f32.
// Strategy: implicit GEMM with running max/argmax; fp32 via packed
// fma.rn.f32x2 (FFMA2) for 2x the scalar-FFMA rate on sm_103a.
// ---------------------------------------------------------------------------

typedef unsigned long long u64;

__device__ __forceinline__ u64 pack2(float lo, float hi) {
    u64 r;
    asm("mov.b64 %0, {%1, %2};" : "=l"(r) : "f"(lo), "f"(hi));
    return r;
}
__device__ __forceinline__ u64 ffma2(u64 a, u64 b, u64 c) {
    u64 d;
    asm("fma.rn.f32x2 %0, %1, %2, %3;" : "=l"(d) : "l"(a), "l"(b), "l"(c));
    return d;
}
__device__ __forceinline__ void unpack2(u64 v, float& lo, float& hi) {
    asm("mov.b64 {%0, %1}, %2;" : "=f"(lo), "=f"(hi) : "l"(v));
}

// Scratch (allocation-free: __device__ globals)
__device__ float g_cnorm[1024];
__device__ float g_xnorm[131072];

// ---------------------------------------------------------------------------
// Row-norm kernels: one warp per 256-float row.
// ---------------------------------------------------------------------------
__global__ void xnorm_kernel(const float* __restrict__ src, int rows) {
    int warp = (blockIdx.x * blockDim.x + threadIdx.x) >> 5;
    int lane = threadIdx.x & 31;
    if (warp >= rows) return;
    const float4* r = (const float4*)(src + (size_t)warp * 256);
    float4 a = r[lane];
    float4 b = r[lane + 32];
    float s = a.x * a.x + a.y * a.y + a.z * a.z + a.w * a.w +
              b.x * b.x + b.y * b.y + b.z * b.z + b.w * b.w;
#pragma unroll
    for (int o = 16; o; o >>= 1) s += __shfl_xor_sync(0xffffffffu, s, o);
    if (lane == 0) g_xnorm[warp] = s;
}

__global__ void cnorm_kernel(const float* __restrict__ src, int rows) {
    int warp = (blockIdx.x * blockDim.x + threadIdx.x) >> 5;
    int lane = threadIdx.x & 31;
    if (warp >= rows) return;
    const float4* r = (const float4*)(src + (size_t)warp * 256);
    float4 a = r[lane];
    float4 b = r[lane + 32];
    float s = a.x * a.x + a.y * a.y + a.z * a.z + a.w * a.w +
              b.x * b.x + b.y * b.y + b.z * b.z + b.w * b.w;
#pragma unroll
    for (int o = 16; o; o >>= 1) s += __shfl_xor_sync(0xffffffffu, s, o);
    if (lane == 0) g_cnorm[warp] = s;
}

// ---------------------------------------------------------------------------
// Main kernel.
//   Block: 256 threads (tx = tid&15, ty = tid>>4), BM=128 rows, BN=128 cents.
//   Per thread: TM=8 rows (ty*8..+7), TN=8 cols STRIDED (tx + 16*i).
//   D chunked by 16, double-buffered smem, d-major tiles xs[d][m], cs[d][n].
//   Accumulators: row-paired f32x2 (4 pairs x 8 cols = 32 u64).
// ---------------------------------------------------------------------------
__global__ __launch_bounds__(256) void assign_kernel(
    const float* __restrict__ x, const float* __restrict__ c,
    float* __restrict__ out, int Ntot) {
    __shared__ __align__(16) float xs[2][16 * 128];
    __shared__ __align__(16) float cs[2][16 * 128];

    const int tid = threadIdx.x;
    const int tx = tid & 15;
    const int ty = tid >> 4;
    const int rowBase = blockIdx.x * 128;

    // Staging-load mapping: thread covers float4 indices 2*tid, 2*tid+1 over
    // (m in 0..127) x (u in 0..3), i.e. 2048 floats = one 16x128 chunk.
    const int i0 = tid * 2, i1 = tid * 2 + 1;
    const int m0 = i0 >> 2, u0 = i0 & 3;
    const int m1 = i1 >> 2, u1 = i1 & 3;

    const float* xp0 = x + (size_t)(rowBase + m0) * 256 + u0 * 4;
    const float* xp1 = x + (size_t)(rowBase + m1) * 256 + u1 * 4;

    u64 acc[4][8];
    float bestv[8];
    int besti[8];
#pragma unroll
    for (int p = 0; p < 8; p++) { bestv[p] = -3.4e38f; besti[p] = 0; }

    float4 X0, X1, C0, C1;
    int buf = 0;

    for (int kt = 0; kt < 8; ++kt) {
        const int cBase = kt * 128;
        const float* cp0 = c + (size_t)(cBase + m0) * 256 + u0 * 4;
        const float* cp1 = c + (size_t)(cBase + m1) * 256 + u1 * 4;

#pragma unroll
        for (int p = 0; p < 4; p++)
#pragma unroll
            for (int i = 0; i < 8; i++) acc[p][i] = 0ull;

        float cn[8];
#pragma unroll
        for (int i = 0; i < 8; i++) cn[i] = g_cnorm[cBase + tx + 16 * i];

        // ---- load chunk dc = 0 ----
        X0 = *(const float4*)(xp0);
        X1 = *(const float4*)(xp1);
        C0 = *(const float4*)(cp0);
        C1 = *(const float4*)(cp1);
        {
            float* xd = xs[buf];
            xd[(u0 * 4 + 0) * 128 + m0] = X0.x; xd[(u0 * 4 + 1) * 128 + m0] = X0.y;
            xd[(u0 * 4 + 2) * 128 + m0] = X0.z; xd[(u0 * 4 + 3) * 128 + m0] = X0.w;
            xd[(u1 * 4 + 0) * 128 + m1] = X1.x; xd[(u1 * 4 + 1) * 128 + m1] = X1.y;
            xd[(u1 * 4 + 2) * 128 + m1] = X1.z; xd[(u1 * 4 + 3) * 128 + m1] = X1.w;
            float* cd = cs[buf];
            cd[(u0 * 4 + 0) * 128 + m0] = C0.x; cd[(u0 * 4 + 1) * 128 + m0] = C0.y;
            cd[(u0 * 4 + 2) * 128 + m0] = C0.z; cd[(u0 * 4 + 3) * 128 + m0] = C0.w;
            cd[(u1 * 4 + 0) * 128 + m1] = C1.x; cd[(u1 * 4 + 1) * 128 + m1] = C1.y;
            cd[(u1 * 4 + 2) * 128 + m1] = C1.z; cd[(u1 * 4 + 3) * 128 + m1] = C1.w;
        }
        __syncthreads();

        for (int dc = 0; dc < 16; ++dc) {
            // ---- issue next chunk's global loads (latency hidden by compute)
            if (dc < 15) {
                const int dcb = (dc + 1) * 16;
                X0 = *(const float4*)(xp0 + dcb);
                X1 = *(const float4*)(xp1 + dcb);
                C0 = *(const float4*)(cp0 + dcb);
                C1 = *(const float4*)(cp1 + dcb);
            }

            // ---- compute current chunk ----
            const float* xbuf = xs[buf];
            const float* cbuf = cs[buf];
#pragma unroll
            for (int kk = 0; kk < 16; ++kk) {
                const float* xrow = xbuf + kk * 128 + ty * 8;
                // A: two 16B loads = 4 row-pairs (broadcast, conflict-free)
                ulonglong2 A0 = *(const ulonglong2*)(xrow);
                ulonglong2 A1 = *(const ulonglong2*)(xrow + 4);
                // B: 8 strided scalar loads (conflict-free: banks = tx+16i)
                const float* crow = cbuf + kk * 128 + tx;
                u64 bd[8];
#pragma unroll
                for (int i = 0; i < 8; i++) {
                    float b = crow[16 * i];
                    bd[i] = pack2(b, b);
                }
                u64 ap0 = A0.x, ap1 = A0.y, ap2 = A1.x, ap3 = A1.y;
#pragma unroll
                for (int i = 0; i < 8; i++) {
                    acc[0][i] = ffma2(ap0, bd[i], acc[0][i]);
                    acc[1][i] = ffma2(ap1, bd[i], acc[1][i]);
                    acc[2][i] = ffma2(ap2, bd[i], acc[2][i]);
                    acc[3][i] = ffma2(ap3, bd[i], acc[3][i]);
                }
            }

            // ---- store staged next chunk into the other buffer ----
            if (dc < 15) {
                int nb = buf ^ 1;
                float* xd = xs[nb];
                xd[(u0 * 4 + 0) * 128 + m0] = X0.x; xd[(u0 * 4 + 1) * 128 + m0] = X0.y;
                xd[(u0 * 4 + 2) * 128 + m0] = X0.z; xd[(u0 * 4 + 3) * 128 + m0] = X0.w;
                xd[(u1 * 4 + 0) * 128 + m1] = X1.x; xd[(u1 * 4 + 1) * 128 + m1] = X1.y;
                xd[(u1 * 4 + 2) * 128 + m1] = X1.z; xd[(u1 * 4 + 3) * 128 + m1] = X1.w;
                float* cd = cs[nb];
                cd[(u0 * 4 + 0) * 128 + m0] = C0.x; cd[(u0 * 4 + 1) * 128 + m0] = C0.y;
                cd[(u0 * 4 + 2) * 128 + m0] = C0.z; cd[(u0 * 4 + 3) * 128 + m0] = C0.w;
                cd[(u1 * 4 + 0) * 128 + m1] = C1.x; cd[(u1 * 4 + 1) * 128 + m1] = C1.y;
                cd[(u1 * 4 + 2) * 128 + m1] = C1.z; cd[(u1 * 4 + 3) * 128 + m1] = C1.w;
            }
            __syncthreads();
            buf ^= 1;
        }

        // ---- K-tile epilogue: sim = 2*acc - |c|^2, update running argmax ----
#pragma unroll
        for (int p = 0; p < 4; p++) {
#pragma unroll
            for (int i = 0; i < 8; i++) {
                float lo, hi;
                unpack2(acc[p][i], lo, hi);
                int n = cBase + tx + 16 * i;
                float v0 = 2.0f * lo - cn[i];
                float v1 = 2.0f * hi - cn[i];
                if (v0 > bestv[2 * p])     { bestv[2 * p] = v0;     besti[2 * p] = n; }
                if (v1 > bestv[2 * p + 1]) { bestv[2 * p + 1] = v1; besti[2 * p + 1] = n; }
            }
        }
    }

    // ---- cross-thread (tx) reduction via reused smem ----
    __syncthreads();
    float* redv = &xs[0][0];    // 2048 floats needed, 4096 available
    int* redi = (int*)&cs[0][0];
#pragma unroll
    for (int p = 0; p < 8; p++) {
        int row = ty * 8 + p;
        redv[row * 16 + tx] = bestv[p];
        redi[row * 16 + tx] = besti[p];
    }
    __syncthreads();
    if (tid < 128) {
        int row = tid;
        float bv = redv[row * 16];
        int bi = redi[row * 16];
#pragma unroll
        for (int j = 1; j < 16; j++) {
            float v = redv[row * 16 + j];
            int id = redi[row * 16 + j];
            if (v > bv || (v == bv && id < bi)) { bv = v; bi = id; }
        }
        int g = rowBase + row;
        out[g] = bv - g_xnorm[g];          // max_sim
        out[Ntot + g] = (float)bi;         // label as float
    }
}

// ---------------------------------------------------------------------------
extern "C" void kernel_launch(void* const* d_in, const int* in_sizes, int n_in,
                              void* d_out, int out_size) {
    const float* x = (const float*)d_in[0];
    const float* c = (const float*)d_in[1];
    float* out = (float*)d_out;

    const int D = 256;
    const int N = in_sizes[0] / D;   // 131072
    const int K = in_sizes[1] / D;   // 1024

    // Norms (one warp per row; 8 rows per 256-thread block)
    cnorm_kernel<<<(K + 7) / 8, 256>>>(c, K);
    xnorm_kernel<<<(N + 7) / 8, 256>>>(x, N);

    // Main assignment: BM=128 rows per block
    assign_kernel<<<N / 128, 256>>>(x, c, out, N);
}

// round 13
// speedup vs baseline: 1.9244x; 1.9243x over previous
#include <cuda_runtime.h>
#include <cuda_bf16.h>
#include <cstdint>

#define DEVINL __device__ __forceinline__

// ---------------- problem constants ----------------
#define NROWS 131072
#define KC    1024
#define DDIM  256
#define FIXCAP 8192
#define GAP_THR 0.05f

// ---------------- global scratch (allocation-free) ----------------
__device__ __align__(1024) __nv_bfloat16 g_xhi[NROWS * DDIM];
__device__ __align__(1024) __nv_bfloat16 g_xlo[NROWS * DDIM];
__device__ __align__(1024) __nv_bfloat16 g_chi[KC * DDIM];   // holds bf16(2c) hi
__device__ __align__(1024) __nv_bfloat16 g_clo[KC * DDIM];   // holds bf16(2c) lo
__device__ float g_xn[NROWS];
__device__ float g_cn[KC];
__device__ int   g_fix_count;
__device__ int   g_fix_list[FIXCAP];

// ---------------- PTX helpers (sm_80-baseline only; NO 'a' features) -------
DEVINL uint32_t s2u(const void* p) {
    uint32_t a;
    asm("{ .reg .u64 t; cvta.to.shared.u64 t, %1; cvt.u32.u64 %0, t; }"
        : "=r"(a) : "l"(p));
    return a;
}
DEVINL void ldsm4(uint32_t* r, uint32_t addr) {
    asm volatile("ldmatrix.sync.aligned.m8n8.x4.shared.b16 {%0,%1,%2,%3}, [%4];"
                 : "=r"(r[0]), "=r"(r[1]), "=r"(r[2]), "=r"(r[3]) : "r"(addr));
}
DEVINL void mma_bf16(float* d, const uint32_t* a, const uint32_t* b) {
    asm volatile(
        "mma.sync.aligned.m16n8k16.row.col.f32.bf16.bf16.f32 "
        "{%0,%1,%2,%3}, {%4,%5,%6,%7}, {%8,%9}, {%0,%1,%2,%3};"
        : "+f"(d[0]), "+f"(d[1]), "+f"(d[2]), "+f"(d[3])
        : "r"(a[0]), "r"(a[1]), "r"(a[2]), "r"(a[3]), "r"(b[0]), "r"(b[1]));
}

// ---------------- split pre-kernels ----------------
DEVINL uint32_t packb(__nv_bfloat16 a, __nv_bfloat16 b) {
    return (uint32_t)__bfloat16_as_ushort(a) | ((uint32_t)__bfloat16_as_ushort(b) << 16);
}
DEVINL void split4(float4 v, float scale, uint2& hi, uint2& lo) {
    float f0 = v.x * scale, f1 = v.y * scale, f2 = v.z * scale, f3 = v.w * scale;
    __nv_bfloat16 h0 = __float2bfloat16_rn(f0), h1 = __float2bfloat16_rn(f1);
    __nv_bfloat16 h2 = __float2bfloat16_rn(f2), h3 = __float2bfloat16_rn(f3);
    __nv_bfloat16 l0 = __float2bfloat16_rn(f0 - __bfloat162float(h0));
    __nv_bfloat16 l1 = __float2bfloat16_rn(f1 - __bfloat162float(h1));
    __nv_bfloat16 l2 = __float2bfloat16_rn(f2 - __bfloat162float(h2));
    __nv_bfloat16 l3 = __float2bfloat16_rn(f3 - __bfloat162float(h3));
    hi.x = packb(h0, h1); hi.y = packb(h2, h3);
    lo.x = packb(l0, l1); lo.y = packb(l2, l3);
}

__global__ void split_x_kernel(const float* __restrict__ x) {
    int w = (blockIdx.x * blockDim.x + threadIdx.x) >> 5;
    int lane = threadIdx.x & 31;
    const float4* r = (const float4*)(x + (size_t)w * DDIM);
    float4 a = r[lane], b = r[lane + 32];
    float s = a.x * a.x + a.y * a.y + a.z * a.z + a.w * a.w +
              b.x * b.x + b.y * b.y + b.z * b.z + b.w * b.w;
#pragma unroll
    for (int o = 16; o; o >>= 1) s += __shfl_xor_sync(0xffffffffu, s, o);
    if (lane == 0) g_xn[w] = s;
    uint2 hA, lA, hB, lB;
    split4(a, 1.0f, hA, lA);
    split4(b, 1.0f, hB, lB);
    uint2* ph = (uint2*)(g_xhi + (size_t)w * DDIM);
    uint2* pl = (uint2*)(g_xlo + (size_t)w * DDIM);
    ph[lane] = hA; ph[lane + 32] = hB;
    pl[lane] = lA; pl[lane + 32] = lB;
}

__global__ void split_c_kernel(const float* __restrict__ c) {
    if (blockIdx.x == 0 && threadIdx.x == 0) g_fix_count = 0;  // reset per replay
    int w = (blockIdx.x * blockDim.x + threadIdx.x) >> 5;
    int lane = threadIdx.x & 31;
    const float4* r = (const float4*)(c + (size_t)w * DDIM);
    float4 a = r[lane], b = r[lane + 32];
    float s = a.x * a.x + a.y * a.y + a.z * a.z + a.w * a.w +
              b.x * b.x + b.y * b.y + b.z * b.z + b.w * b.w;
#pragma unroll
    for (int o = 16; o; o >>= 1) s += __shfl_xor_sync(0xffffffffu, s, o);
    if (lane == 0) g_cn[w] = s;
    uint2 hA, lA, hB, lB;
    split4(a, 2.0f, hA, lA);   // scaled by 2: sim = x.(2c) - |c|^2 - |x|^2
    split4(b, 2.0f, hB, lB);
    uint2* ph = (uint2*)(g_chi + (size_t)w * DDIM);
    uint2* pl = (uint2*)(g_clo + (size_t)w * DDIM);
    ph[lane] = hA; ph[lane + 32] = hB;
    pl[lane] = lA; pl[lane + 32] = lB;
}

// ---------------- main HMMA kernel ----------------
// smem (dynamic, bytes):
//   XHI: 0       .. 73728   (4 d-chunks x [128 rows x 72 bf16], row stride 144B)
//   XLO: 73728   .. 147456
//   CBUF: 147456 .. 221184  (2 bufs x { hi[128x72], lo[128x72] } = 2 x 36864)
//   CN:  221184  .. 225280  (1024 f32)
#define XHI_OFF  0
#define XLO_OFF  73728
#define CBUF_OFF 147456
#define CN_OFF   221184
#define SMEM_SZ  225280
#define CHUNK_B  18432          /* 128*144 */
#define ROW_B    144

__global__ __launch_bounds__(256, 1) void assign_mma(float* __restrict__ out, int Ntot) {
    extern __shared__ char smem[];
    const uint32_t sb = s2u(smem);
    const int tid = threadIdx.x;
    const int wid = tid >> 5;
    const int lane = tid & 31;
    const int warp_m = wid & 3;      // 0..3 -> 32-row slice
    const int warp_n = wid >> 2;     // 0..1 -> 64-col slice
    const int rowBase = blockIdx.x * 128;

    // per-lane ldmatrix offsets (g = lane/8 selects the 8x8 sub-matrix)
    const int g8 = lane >> 3, r8 = lane & 7;
    const uint32_t offA = (uint32_t)((warp_m * 32 + r8 + (g8 & 1) * 8) * ROW_B + (g8 >> 1) * 16);
    const uint32_t offB = (uint32_t)((warp_n * 64 + r8 + (g8 >> 1) * 8) * ROW_B + (g8 & 1) * 16);

    // ---- prologue: X tiles (hi+lo), C chunk 0, cn table ----
    {
        const uint4* gxh = (const uint4*)g_xhi + (size_t)rowBase * 32;
        const uint4* gxl = (const uint4*)g_xlo + (size_t)rowBase * 32;
#pragma unroll
        for (int i = 0; i < 16; i++) {
            int idx = tid + i * 256;           // 0..4095
            int row = idx >> 5, c8 = idx & 31;
            int dch = c8 >> 3, cc = c8 & 7;
            uint32_t so = (uint32_t)(dch * CHUNK_B + row * ROW_B + cc * 16);
            *(uint4*)(smem + XHI_OFF + so) = gxh[(size_t)row * 32 + c8];
            *(uint4*)(smem + XLO_OFF + so) = gxl[(size_t)row * 32 + c8];
        }
        // C chunk 0 (nt=0, dc=0) into buf 0
        const uint4* gch = (const uint4*)g_chi;
        const uint4* gcl = (const uint4*)g_clo;
#pragma unroll
        for (int i = 0; i < 4; i++) {
            int idx = tid + i * 256;           // 0..1023
            int row = idx >> 3, c8 = idx & 7;
            uint32_t so = (uint32_t)(row * ROW_B + c8 * 16);
            *(uint4*)(smem + CBUF_OFF + so)         = gch[(size_t)row * 32 + c8];
            *(uint4*)(smem + CBUF_OFF + CHUNK_B + so) = gcl[(size_t)row * 32 + c8];
        }
        ((float4*)(smem + CN_OFF))[tid] = ((const float4*)g_cn)[tid];
    }
    __syncthreads();

    float acc[2][8][4];
#pragma unroll
    for (int mt = 0; mt < 2; mt++)
#pragma unroll
        for (int j = 0; j < 8; j++)
#pragma unroll
            for (int e = 0; e < 4; e++) acc[mt][j][e] = 0.f;

    float bestv[4], secv[4];
    int besti[4];
#pragma unroll
    for (int t = 0; t < 4; t++) { bestv[t] = -3.4e38f; secv[t] = -3.4e38f; besti[t] = 0; }

    const float* cnS = (const float*)(smem + CN_OFF);

    for (int q = 0; q < 32; q++) {
        const int nt = q >> 2, dc = q & 3, buf = q & 1;

        // prefetch next C chunk to regs
        uint4 vh[4], vl[4];
        if (q < 31) {
            const int nt2 = (q + 1) >> 2, dc2 = (q + 1) & 3;
            const uint4* gch = (const uint4*)g_chi + (size_t)nt2 * 128 * 32 + dc2 * 8;
            const uint4* gcl = (const uint4*)g_clo + (size_t)nt2 * 128 * 32 + dc2 * 8;
#pragma unroll
            for (int i = 0; i < 4; i++) {
                int idx = tid + i * 256;
                int row = idx >> 3, c8 = idx & 7;
                vh[i] = gch[(size_t)row * 32 + c8];
                vl[i] = gcl[(size_t)row * 32 + c8];
            }
        }

        // ---- compute: 4 k16 steps over this 64-dim chunk ----
#pragma unroll
        for (int ks = 0; ks < 4; ks++) {
            uint32_t ahi[2][4], alo[2][4];
            const uint32_t xb = sb + (uint32_t)(XHI_OFF + dc * CHUNK_B + ks * 32);
            ldsm4(ahi[0], xb + offA);
            ldsm4(ahi[1], xb + 2304 + offA);
            ldsm4(alo[0], xb + (XLO_OFF - XHI_OFF) + offA);
            ldsm4(alo[1], xb + (XLO_OFF - XHI_OFF) + 2304 + offA);
#pragma unroll
            for (int nq = 0; nq < 4; nq++) {
                uint32_t bh[4], bl[4];
                const uint32_t cb = sb + (uint32_t)(CBUF_OFF + buf * (2 * CHUNK_B) + nq * 2304 + ks * 32);
                ldsm4(bh, cb + offB);
                ldsm4(bl, cb + CHUNK_B + offB);
#pragma unroll
                for (int mt = 0; mt < 2; mt++) {
                    mma_bf16(acc[mt][2 * nq],     ahi[mt], bh);
                    mma_bf16(acc[mt][2 * nq],     alo[mt], bh);
                    mma_bf16(acc[mt][2 * nq],     ahi[mt], bl);
                    mma_bf16(acc[mt][2 * nq + 1], ahi[mt], bh + 2);
                    mma_bf16(acc[mt][2 * nq + 1], alo[mt], bh + 2);
                    mma_bf16(acc[mt][2 * nq + 1], ahi[mt], bl + 2);
                }
            }
        }

        // ---- per-n-tile epilogue: fold cn, track top-2, clear accs ----
        if (dc == 3) {
#pragma unroll
            for (int mt = 0; mt < 2; mt++)
#pragma unroll
                for (int j = 0; j < 8; j++) {
                    int cg = nt * 128 + warp_n * 64 + j * 8 + (lane & 3) * 2;
                    float cn0 = cnS[cg], cn1 = cnS[cg + 1];
                    float* a = acc[mt][j];
                    float v0 = a[0] - cn0, v1 = a[1] - cn1;
                    float v2 = a[2] - cn0, v3 = a[3] - cn1;
                    int t0 = mt * 2, t1 = mt * 2 + 1;
                    if (v0 > bestv[t0]) { secv[t0] = bestv[t0]; bestv[t0] = v0; besti[t0] = cg; }
                    else if (v0 > secv[t0]) secv[t0] = v0;
                    if (v1 > bestv[t0]) { secv[t0] = bestv[t0]; bestv[t0] = v1; besti[t0] = cg + 1; }
                    else if (v1 > secv[t0]) secv[t0] = v1;
                    if (v2 > bestv[t1]) { secv[t1] = bestv[t1]; bestv[t1] = v2; besti[t1] = cg; }
                    else if (v2 > secv[t1]) secv[t1] = v2;
                    if (v3 > bestv[t1]) { secv[t1] = bestv[t1]; bestv[t1] = v3; besti[t1] = cg + 1; }
                    else if (v3 > secv[t1]) secv[t1] = v3;
                    a[0] = a[1] = a[2] = a[3] = 0.f;
                }
        }

        // ---- stage next chunk into the other buffer ----
        if (q < 31) {
            char* db = smem + CBUF_OFF + ((q + 1) & 1) * (2 * CHUNK_B);
#pragma unroll
            for (int i = 0; i < 4; i++) {
                int idx = tid + i * 256;
                int row = idx >> 3, c8 = idx & 7;
                uint32_t so = (uint32_t)(row * ROW_B + c8 * 16);
                *(uint4*)(db + so) = vh[i];
                *(uint4*)(db + CHUNK_B + so) = vl[i];
            }
        }
        __syncthreads();
    }

    // ---- cross-lane top-2 reduce (lanes sharing a row: same lane/4) ----
#pragma unroll
    for (int off = 1; off < 4; off <<= 1) {
#pragma unroll
        for (int t = 0; t < 4; t++) {
            float ob = __shfl_xor_sync(0xffffffffu, bestv[t], off);
            float os = __shfl_xor_sync(0xffffffffu, secv[t], off);
            int oi = __shfl_xor_sync(0xffffffffu, besti[t], off);
            if (ob > bestv[t] || (ob == bestv[t] && oi < besti[t])) {
                secv[t] = fmaxf(bestv[t], os);
                bestv[t] = ob; besti[t] = oi;
            } else {
                secv[t] = fmaxf(secv[t], ob);
            }
        }
    }

    // ---- cross-warp (warp_n) reduce via smem (reuse C buffer area) ----
    float* redB = (float*)(smem + CBUF_OFF);            // [2][128]
    float* redS = (float*)(smem + CBUF_OFF + 1024);     // [2][128]
    int*   redI = (int*)  (smem + CBUF_OFF + 2048);     // [2][128]
    if ((lane & 3) == 0) {
#pragma unroll
        for (int t = 0; t < 4; t++) {
            int row = warp_m * 32 + (t >> 1) * 16 + (lane >> 2) + (t & 1) * 8;
            redB[warp_n * 128 + row] = bestv[t];
            redS[warp_n * 128 + row] = secv[t];
            redI[warp_n * 128 + row] = besti[t];
        }
    }
    __syncthreads();
    if (tid < 128) {
        int row = tid;
        float b0 = redB[row], s0 = redS[row];
        int i0 = redI[row];
        float b1 = redB[128 + row], s1 = redS[128 + row];
        int i1 = redI[128 + row];
        float B, S; int I;
        if (b1 > b0 || (b1 == b0 && i1 < i0)) { B = b1; I = i1; S = fmaxf(b0, s1); }
        else                                  { B = b0; I = i0; S = fmaxf(s0, b1); }
        int g = rowBase + row;
        out[g] = B - g_xn[g];
        out[Ntot + g] = (float)I;
        if (B - S < GAP_THR) {
            int p = atomicAdd(&g_fix_count, 1);
            if (p < FIXCAP) g_fix_list[p] = g;
        }
    }
}

// ---------------- exact fp32 fixup for near-tie rows ----------------
__global__ __launch_bounds__(128) void fix_kernel(
    const float* __restrict__ x, const float* __restrict__ c,
    float* __restrict__ out, int Ntot) {
    int cnt = g_fix_count;
    if (cnt > FIXCAP) cnt = FIXCAP;
    if ((int)blockIdx.x >= cnt) return;
    int row = g_fix_list[blockIdx.x];

    __shared__ float xs[DDIM];
    __shared__ float rb[128];
    __shared__ int ri[128];
    int t = threadIdx.x;
    if (t < 64) ((float4*)xs)[t] = ((const float4*)(x + (size_t)row * DDIM))[t];
    __syncthreads();

    float best = -3.4e38f;
    int bi = 0;
    const float4* xr = (const float4*)xs;
    for (int k = t; k < KC; k += 128) {
        const float4* cr = (const float4*)(c + (size_t)k * DDIM);
        float d0 = 0.f, d1 = 0.f, d2 = 0.f, d3 = 0.f;
#pragma unroll 8
        for (int i = 0; i < 64; i++) {
            float4 a = xr[i], b = cr[i];
            d0 += a.x * b.x; d1 += a.y * b.y; d2 += a.z * b.z; d3 += a.w * b.w;
        }
        float sim = 2.0f * ((d0 + d1) + (d2 + d3)) - g_cn[k];
        if (sim > best || (sim == best && k < bi)) { best = sim; bi = k; }
    }
    rb[t] = best; ri[t] = bi;
    __syncthreads();
    for (int s = 64; s; s >>= 1) {
        if (t < s) {
            float v = rb[t + s]; int i2 = ri[t + s];
            if (v > rb[t] || (v == rb[t] && i2 < ri[t])) { rb[t] = v; ri[t] = i2; }
        }
        __syncthreads();
    }
    if (t == 0) {
        out[row] = rb[0] - g_xn[row];
        out[Ntot + row] = (float)ri[0];
    }
}

// ---------------------------------------------------------------------------
extern "C" void kernel_launch(void* const* d_in, const int* in_sizes, int n_in,
                              void* d_out, int out_size) {
    const float* x = (const float*)d_in[0];
    const float* c = (const float*)d_in[1];
    float* out = (float*)d_out;

    const int D = 256;
    const int N = in_sizes[0] / D;   // 131072
    const int K = in_sizes[1] / D;   // 1024

    static int smem_set = 0;
    if (!smem_set) {
        cudaFuncSetAttribute((const void*)assign_mma,
                             cudaFuncAttributeMaxDynamicSharedMemorySize, SMEM_SZ);
        smem_set = 1;
    }

    split_c_kernel<<<K / 8, 256>>>(c);      // also resets g_fix_count
    split_x_kernel<<<N / 8, 256>>>(x);
    assign_mma<<<N / 128, 256, SMEM_SZ>>>(out, N);
    fix_kernel<<<FIXCAP, 128>>>(x, c, out, N);
}

// round 14
// speedup vs baseline: 2.2039x; 1.1452x over previous
#include <cuda_runtime.h>
#include <cuda_bf16.h>
#include <cstdint>

#define DEVINL __device__ __forceinline__

// ---------------- problem constants ----------------
#define NROWS 131072
#define KC    1024
#define DDIM  256
#define FIXCAP 4096
#define GAP_THR 0.012f

// ---------------- global scratch (allocation-free) ----------------
__device__ __align__(1024) __nv_bfloat16 g_chi[KC * DDIM];   // bf16(2c) hi
__device__ __align__(1024) __nv_bfloat16 g_clo[KC * DDIM];   // bf16(2c) lo
__device__ float g_cn[KC];
__device__ int   g_fix_count;
__device__ int   g_fix_list[FIXCAP];

// ---------------- PTX helpers (sm_80-baseline only) ----------------
DEVINL uint32_t s2u(const void* p) {
    uint32_t a;
    asm("{ .reg .u64 t; cvta.to.shared.u64 t, %1; cvt.u32.u64 %0, t; }"
        : "=r"(a) : "l"(p));
    return a;
}
DEVINL void ldsm4(uint32_t* r, uint32_t addr) {
    asm volatile("ldmatrix.sync.aligned.m8n8.x4.shared.b16 {%0,%1,%2,%3}, [%4];"
                 : "=r"(r[0]), "=r"(r[1]), "=r"(r[2]), "=r"(r[3]) : "r"(addr));
}
DEVINL void mma_bf16(float* d, const uint32_t* a, const uint32_t* b) {
    asm volatile(
        "mma.sync.aligned.m16n8k16.row.col.f32.bf16.bf16.f32 "
        "{%0,%1,%2,%3}, {%4,%5,%6,%7}, {%8,%9}, {%0,%1,%2,%3};"
        : "+f"(d[0]), "+f"(d[1]), "+f"(d[2]), "+f"(d[3])
        : "r"(a[0]), "r"(a[1]), "r"(a[2]), "r"(a[3]), "r"(b[0]), "r"(b[1]));
}
DEVINL void cp16(uint32_t saddr, const void* gaddr) {
    asm volatile("cp.async.cg.shared.global [%0], [%1], 16;"
                 :: "r"(saddr), "l"(gaddr) : "memory");
}
DEVINL void cp_commit() { asm volatile("cp.async.commit_group;" ::: "memory"); }
DEVINL void cp_wait0()  { asm volatile("cp.async.wait_group 0;"  ::: "memory"); }

// ---------------- split helpers ----------------
DEVINL uint32_t packb(__nv_bfloat16 a, __nv_bfloat16 b) {
    return (uint32_t)__bfloat16_as_ushort(a) | ((uint32_t)__bfloat16_as_ushort(b) << 16);
}
DEVINL void split4(float4 v, float scale, uint2& hi, uint2& lo) {
    float f0 = v.x * scale, f1 = v.y * scale, f2 = v.z * scale, f3 = v.w * scale;
    __nv_bfloat16 h0 = __float2bfloat16_rn(f0), h1 = __float2bfloat16_rn(f1);
    __nv_bfloat16 h2 = __float2bfloat16_rn(f2), h3 = __float2bfloat16_rn(f3);
    __nv_bfloat16 l0 = __float2bfloat16_rn(f0 - __bfloat162float(h0));
    __nv_bfloat16 l1 = __float2bfloat16_rn(f1 - __bfloat162float(h1));
    __nv_bfloat16 l2 = __float2bfloat16_rn(f2 - __bfloat162float(h2));
    __nv_bfloat16 l3 = __float2bfloat16_rn(f3 - __bfloat162float(h3));
    hi.x = packb(h0, h1); hi.y = packb(h2, h3);
    lo.x = packb(l0, l1); lo.y = packb(l2, l3);
}

// centroid split (tiny: 1024 rows)
__global__ void split_c_kernel(const float* __restrict__ c) {
    if (blockIdx.x == 0 && threadIdx.x == 0) g_fix_count = 0;  // reset per replay
    int w = (blockIdx.x * blockDim.x + threadIdx.x) >> 5;
    int lane = threadIdx.x & 31;
    const float4* r = (const float4*)(c + (size_t)w * DDIM);
    float4 a = r[lane], b = r[lane + 32];
    float s = a.x * a.x + a.y * a.y + a.z * a.z + a.w * a.w +
              b.x * b.x + b.y * b.y + b.z * b.z + b.w * b.w;
#pragma unroll
    for (int o = 16; o; o >>= 1) s += __shfl_xor_sync(0xffffffffu, s, o);
    if (lane == 0) g_cn[w] = s;
    uint2 hA, lA, hB, lB;
    split4(a, 2.0f, hA, lA);   // pre-scale by 2: sim = x.(2c) - |c|^2 - |x|^2
    split4(b, 2.0f, hB, lB);
    uint2* ph = (uint2*)(g_chi + (size_t)w * DDIM);
    uint2* pl = (uint2*)(g_clo + (size_t)w * DDIM);
    ph[lane] = hA; ph[lane + 32] = hB;
    pl[lane] = lA; pl[lane + 32] = lB;
}

// ---------------- main HMMA kernel ----------------
// smem (dynamic, bytes):
//   XHI: 0       .. 73728   (4 d-chunks x [128 rows x 72 bf16], row stride 144B)
//   XLO: 73728   .. 147456
//   CBUF:147456  .. 221184  (2 bufs x { hi[128x72], lo[128x72] } = 2 x 36864)
//   CN:  221184  .. 225280  (1024 f32)
//   XN:  225280  .. 225792  (128 f32 row norms)
#define XHI_OFF  0
#define XLO_OFF  73728
#define CBUF_OFF 147456
#define CN_OFF   221184
#define XN_OFF   225280
#define SMEM_SZ  225792
#define CHUNK_B  18432          /* 128*144 */
#define ROW_B    144

__global__ __launch_bounds__(256, 1) void assign_mma(
    const float* __restrict__ x, float* __restrict__ out, int Ntot) {
    extern __shared__ char smem[];
    const uint32_t sb = s2u(smem);
    const int tid = threadIdx.x;
    const int wid = tid >> 5;
    const int lane = tid & 31;
    const int warp_m = wid & 3;      // 0..3 -> 32-row slice
    const int warp_n = wid >> 2;     // 0..1 -> 64-col slice
    const int rowBase = blockIdx.x * 128;

    // per-lane ldmatrix offsets
    const int g8 = lane >> 3, r8 = lane & 7;
    const uint32_t offA = (uint32_t)((warp_m * 32 + r8 + (g8 & 1) * 8) * ROW_B + (g8 >> 1) * 16);
    const uint32_t offB = (uint32_t)((warp_n * 64 + r8 + (g8 >> 1) * 8) * ROW_B + (g8 & 1) * 16);

    // staging index map for C chunks (8 cp.async per thread)
    const int crow = tid >> 3, cc8 = tid & 7;           // used with +i*32 rows

    // ---- prologue ----
    // (1) async-stage C chunk q=0 into buf0 + cn table
    {
        const char* gh = (const char*)(g_chi) + ((size_t)crow * 256 + (size_t)cc8 * 8) * 2;
        const char* gl = (const char*)(g_clo) + ((size_t)crow * 256 + (size_t)cc8 * 8) * 2;
        uint32_t so = sb + CBUF_OFF + (uint32_t)(crow * ROW_B + cc8 * 16);
#pragma unroll
        for (int i = 0; i < 4; i++) {
            cp16(so + (uint32_t)(i * 32 * ROW_B), gh + (size_t)i * 32 * 512);
            cp16(so + (uint32_t)(i * 32 * ROW_B) + CHUNK_B, gl + (size_t)i * 32 * 512);
        }
        cp16(sb + CN_OFF + (uint32_t)tid * 16, (const char*)g_cn + tid * 16);
        cp_commit();
    }
    // (2) zero row-norm accumulators
    if (tid < 128) *(float*)(smem + XN_OFF + tid * 4) = 0.f;
    __syncthreads();
    // (3) in-register split of this CTA's X tile + row norms
    {
        const float4* gx = (const float4*)(x + (size_t)rowBase * DDIM);
        float* xnS = (float*)(smem + XN_OFF);
#pragma unroll
        for (int i = 0; i < 32; i++) {
            int idx = tid + i * 256;            // 0..8191
            int row = idx >> 6, c4 = idx & 63;  // 64 float4 per row
            float4 v = gx[(size_t)row * 64 + c4];
            uint2 hi, lo;
            split4(v, 1.0f, hi, lo);
            uint32_t so = (uint32_t)((c4 >> 4) * CHUNK_B + row * ROW_B + (c4 & 15) * 8);
            *(uint2*)(smem + XHI_OFF + so) = hi;
            *(uint2*)(smem + XLO_OFF + so) = lo;
            float s = v.x * v.x + v.y * v.y + v.z * v.z + v.w * v.w;
#pragma unroll
            for (int o = 16; o; o >>= 1) s += __shfl_xor_sync(0xffffffffu, s, o);
            if (lane == 0) atomicAdd(&xnS[row], s);   // row constant per (warp,i)
        }
    }
    cp_wait0();
    __syncthreads();

    float acc[2][8][4];
#pragma unroll
    for (int mt = 0; mt < 2; mt++)
#pragma unroll
        for (int j = 0; j < 8; j++)
#pragma unroll
            for (int e = 0; e < 4; e++) acc[mt][j][e] = 0.f;

    float bestv[4], secv[4];
    int besti[4];
#pragma unroll
    for (int t = 0; t < 4; t++) { bestv[t] = -3.4e38f; secv[t] = -3.4e38f; besti[t] = 0; }

    const float* cnS = (const float*)(smem + CN_OFF);

    for (int q = 0; q < 32; q++) {
        const int nt = q >> 2, dc = q & 3, buf = q & 1;

        // ---- async-stage next C chunk into other buffer ----
        if (q < 31) {
            const int nt2 = (q + 1) >> 2, dc2 = (q + 1) & 3;
            const char* gh = (const char*)(g_chi)
                + ((size_t)(nt2 * 128 + crow) * 256 + (size_t)dc2 * 64 + (size_t)cc8 * 8) * 2;
            const char* gl = (const char*)(g_clo)
                + ((size_t)(nt2 * 128 + crow) * 256 + (size_t)dc2 * 64 + (size_t)cc8 * 8) * 2;
            uint32_t so = sb + CBUF_OFF + (uint32_t)((buf ^ 1) * 2 * CHUNK_B + crow * ROW_B + cc8 * 16);
#pragma unroll
            for (int i = 0; i < 4; i++) {
                cp16(so + (uint32_t)(i * 32 * ROW_B), gh + (size_t)i * 32 * 512);
                cp16(so + (uint32_t)(i * 32 * ROW_B) + CHUNK_B, gl + (size_t)i * 32 * 512);
            }
            cp_commit();
        }

        // ---- compute on current buffer (B double-buffered in regs) ----
        const uint32_t cbase = sb + CBUF_OFF + (uint32_t)(buf * 2 * CHUNK_B);
#pragma unroll
        for (int ks = 0; ks < 4; ks++) {
            uint32_t bh[2][4], bl[2][4];
            // first B of this ks
            {
                uint32_t cb = cbase + (uint32_t)(ks * 32);
                ldsm4(bh[0], cb + offB);
                ldsm4(bl[0], cb + CHUNK_B + offB);
            }
            // A fragments for this ks
            uint32_t ahi[2][4], alo[2][4];
            {
                uint32_t xb = sb + (uint32_t)(dc * CHUNK_B + ks * 32);
                ldsm4(ahi[0], xb + offA);
                ldsm4(ahi[1], xb + 2304 + offA);
                ldsm4(alo[0], xb + XLO_OFF + offA);
                ldsm4(alo[1], xb + XLO_OFF + 2304 + offA);
            }
#pragma unroll
            for (int nq = 0; nq < 4; nq++) {
                const int bc = nq & 1, bn = bc ^ 1;
                if (nq < 3) {   // prefetch next B
                    uint32_t cb = cbase + (uint32_t)((nq + 1) * 2304 + ks * 32);
                    ldsm4(bh[bn], cb + offB);
                    ldsm4(bl[bn], cb + CHUNK_B + offB);
                }
#pragma unroll
                for (int mt = 0; mt < 2; mt++) {
                    mma_bf16(acc[mt][2 * nq],     ahi[mt], bh[bc]);
                    mma_bf16(acc[mt][2 * nq],     alo[mt], bh[bc]);
                    mma_bf16(acc[mt][2 * nq],     ahi[mt], bl[bc]);
                    mma_bf16(acc[mt][2 * nq + 1], ahi[mt], bh[bc] + 2);
                    mma_bf16(acc[mt][2 * nq + 1], alo[mt], bh[bc] + 2);
                    mma_bf16(acc[mt][2 * nq + 1], ahi[mt], bl[bc] + 2);
                }
            }
        }

        // ---- per-n-tile epilogue: fold cn, track top-2, clear accs ----
        if (dc == 3) {
#pragma unroll
            for (int mt = 0; mt < 2; mt++)
#pragma unroll
                for (int j = 0; j < 8; j++) {
                    int cg = nt * 128 + warp_n * 64 + j * 8 + (lane & 3) * 2;
                    float cn0 = cnS[cg], cn1 = cnS[cg + 1];
                    float* a = acc[mt][j];
                    float v0 = a[0] - cn0, v1 = a[1] - cn1;
                    float v2 = a[2] - cn0, v3 = a[3] - cn1;
                    int t0 = mt * 2, t1 = mt * 2 + 1;
                    if (v0 > bestv[t0]) { secv[t0] = bestv[t0]; bestv[t0] = v0; besti[t0] = cg; }
                    else if (v0 > secv[t0]) secv[t0] = v0;
                    if (v1 > bestv[t0]) { secv[t0] = bestv[t0]; bestv[t0] = v1; besti[t0] = cg + 1; }
                    else if (v1 > secv[t0]) secv[t0] = v1;
                    if (v2 > bestv[t1]) { secv[t1] = bestv[t1]; bestv[t1] = v2; besti[t1] = cg; }
                    else if (v2 > secv[t1]) secv[t1] = v2;
                    if (v3 > bestv[t1]) { secv[t1] = bestv[t1]; bestv[t1] = v3; besti[t1] = cg + 1; }
                    else if (v3 > secv[t1]) secv[t1] = v3;
                    a[0] = a[1] = a[2] = a[3] = 0.f;
                }
        }

        cp_wait0();
        __syncthreads();
    }

    // ---- cross-lane top-2 reduce (lanes sharing a row differ in lane&3) ----
#pragma unroll
    for (int off = 1; off < 4; off <<= 1) {
#pragma unroll
        for (int t = 0; t < 4; t++) {
            float ob = __shfl_xor_sync(0xffffffffu, bestv[t], off);
            float os = __shfl_xor_sync(0xffffffffu, secv[t], off);
            int oi = __shfl_xor_sync(0xffffffffu, besti[t], off);
            if (ob > bestv[t] || (ob == bestv[t] && oi < besti[t])) {
                secv[t] = fmaxf(bestv[t], os);
                bestv[t] = ob; besti[t] = oi;
            } else {
                secv[t] = fmaxf(secv[t], ob);
            }
        }
    }

    // ---- cross-warp (warp_n) reduce via smem (reuse C buffer area) ----
    float* redB = (float*)(smem + CBUF_OFF);            // [2][128]
    float* redS = (float*)(smem + CBUF_OFF + 1024);     // [2][128]
    int*   redI = (int*)  (smem + CBUF_OFF + 2048);     // [2][128]
    if ((lane & 3) == 0) {
#pragma unroll
        for (int t = 0; t < 4; t++) {
            int row = warp_m * 32 + (t >> 1) * 16 + (lane >> 2) + (t & 1) * 8;
            redB[warp_n * 128 + row] = bestv[t];
            redS[warp_n * 128 + row] = secv[t];
            redI[warp_n * 128 + row] = besti[t];
        }
    }
    __syncthreads();
    if (tid < 128) {
        int row = tid;
        float b0 = redB[row], s0 = redS[row];
        int i0 = redI[row];
        float b1 = redB[128 + row], s1 = redS[128 + row];
        int i1 = redI[128 + row];
        float B, S; int I;
        if (b1 > b0 || (b1 == b0 && i1 < i0)) { B = b1; I = i1; S = fmaxf(b0, s1); }
        else                                  { B = b0; I = i0; S = fmaxf(s0, b1); }
        int g = rowBase + row;
        out[g] = B - *(const float*)(smem + XN_OFF + row * 4);
        out[Ntot + g] = (float)I;
        if (B - S < GAP_THR) {
            int p = atomicAdd(&g_fix_count, 1);
            if (p < FIXCAP) g_fix_list[p] = g;
        }
    }
}

// ---------------- exact fp32 fixup for near-tie rows ----------------
__global__ __launch_bounds__(256) void fix_kernel(
    const float* __restrict__ x, const float* __restrict__ c,
    float* __restrict__ out, int Ntot) {
    int cnt = g_fix_count;
    if (cnt > FIXCAP) cnt = FIXCAP;
    if ((int)blockIdx.x >= cnt) return;
    int row = g_fix_list[blockIdx.x];

    __shared__ float4 xs4[64];
    __shared__ float rb[256];
    __shared__ int ri[256];
    __shared__ float xnorm;
    int t = threadIdx.x;
    if (t < 64) xs4[t] = ((const float4*)(x + (size_t)row * DDIM))[t];
    __syncthreads();
    // row norm (exact fp32)
    if (t < 64) {
        float4 a = xs4[t];
        rb[t] = a.x * a.x + a.y * a.y + a.z * a.z + a.w * a.w;
    }
    __syncthreads();
    if (t < 32) rb[t] += rb[t + 32];
    __syncthreads();
    if (t == 0) {
        float s = 0.f;
#pragma unroll
        for (int i = 0; i < 32; i++) s += rb[i];
        xnorm = s;
    }
    __syncthreads();

    // 4 centroids per thread, 16 independent FMA chains total
    float best = -3.4e38f;
    int bi = 0;
#pragma unroll
    for (int j = 0; j < 4; j++) {
        int k = t + j * 256;
        const float4* cr = (const float4*)(c + (size_t)k * DDIM);
        float d0 = 0.f, d1 = 0.f, d2 = 0.f, d3 = 0.f;
#pragma unroll 8
        for (int i = 0; i < 64; i++) {
            float4 a = xs4[i], b = cr[i];
            d0 += a.x * b.x; d1 += a.y * b.y; d2 += a.z * b.z; d3 += a.w * b.w;
        }
        float sim = 2.0f * ((d0 + d1) + (d2 + d3)) - g_cn[k];
        if (sim > best || (sim == best && k < bi)) { best = sim; bi = k; }
    }
    rb[t] = best; ri[t] = bi;
    __syncthreads();
    for (int s = 128; s; s >>= 1) {
        if (t < s) {
            float v = rb[t + s]; int i2 = ri[t + s];
            if (v > rb[t] || (v == rb[t] && i2 < ri[t])) { rb[t] = v; ri[t] = i2; }
        }
        __syncthreads();
    }
    if (t == 0) {
        out[row] = rb[0] - xnorm;
        out[Ntot + row] = (float)ri[0];
    }
}

// ---------------------------------------------------------------------------
extern "C" void kernel_launch(void* const* d_in, const int* in_sizes, int n_in,
                              void* d_out, int out_size) {
    const float* x = (const float*)d_in[0];
    const float* c = (const float*)d_in[1];
    float* out = (float*)d_out;

    const int D = 256;
    const int N = in_sizes[0] / D;   // 131072
    const int K = in_sizes[1] / D;   // 1024

    static int smem_set = 0;
    if (!smem_set) {
        cudaFuncSetAttribute((const void*)assign_mma,
                             cudaFuncAttributeMaxDynamicSharedMemorySize, SMEM_SZ);
        smem_set = 1;
    }

    split_c_kernel<<<K / 8, 256>>>(c);      // also resets g_fix_count
    assign_mma<<<N / 128, 256, SMEM_SZ>>>(x, out, N);
    fix_kernel<<<FIXCAP, 256>>>(x, c, out, N);
}

// round 15
// speedup vs baseline: 2.9452x; 1.3364x over previous
#include <cuda_runtime.h>
#include <cuda_fp16.h>
#include <cstdint>

#define DEVINL __device__ __forceinline__

// ---------------- problem constants ----------------
#define NROWS 131072
#define KC    1024
#define DDIM  256
#define FIXCAP 8192
#define GAP_THR 0.045f

// ---------------- global scratch (allocation-free) ----------------
__device__ __align__(1024) __half g_ch[KC * DDIM];   // fp16(2c), single stream
__device__ float g_cn[KC];
__device__ int   g_fix_count;
__device__ int   g_fix_list[FIXCAP];

// ---------------- PTX helpers (sm_80-baseline only) ----------------
DEVINL uint32_t s2u(const void* p) {
    uint32_t a;
    asm("{ .reg .u64 t; cvta.to.shared.u64 t, %1; cvt.u32.u64 %0, t; }"
        : "=r"(a) : "l"(p));
    return a;
}
DEVINL void ldsm4(uint32_t* r, uint32_t addr) {
    asm volatile("ldmatrix.sync.aligned.m8n8.x4.shared.b16 {%0,%1,%2,%3}, [%4];"
                 : "=r"(r[0]), "=r"(r[1]), "=r"(r[2]), "=r"(r[3]) : "r"(addr));
}
DEVINL void mma_f16(float* d, const uint32_t* a, const uint32_t* b) {
    asm volatile(
        "mma.sync.aligned.m16n8k16.row.col.f32.f16.f16.f32 "
        "{%0,%1,%2,%3}, {%4,%5,%6,%7}, {%8,%9}, {%0,%1,%2,%3};"
        : "+f"(d[0]), "+f"(d[1]), "+f"(d[2]), "+f"(d[3])
        : "r"(a[0]), "r"(a[1]), "r"(a[2]), "r"(a[3]), "r"(b[0]), "r"(b[1]));
}
DEVINL void cp16(uint32_t saddr, const void* gaddr) {
    asm volatile("cp.async.cg.shared.global [%0], [%1], 16;"
                 :: "r"(saddr), "l"(gaddr) : "memory");
}
DEVINL void cp_commit() { asm volatile("cp.async.commit_group;" ::: "memory"); }
DEVINL void cp_wait2()  { asm volatile("cp.async.wait_group 2;"  ::: "memory"); }
DEVINL void cp_wait0()  { asm volatile("cp.async.wait_group 0;"  ::: "memory"); }

// ---------------- split helpers ----------------
DEVINL uint32_t packh(__half a, __half b) {
    return (uint32_t)__half_as_ushort(a) | ((uint32_t)__half_as_ushort(b) << 16);
}
// x -> fp16 hi + fp16 lo (x captured to ~2^-22)
DEVINL void split4h(float4 v, uint2& hi, uint2& lo) {
    __half h0 = __float2half_rn(v.x), h1 = __float2half_rn(v.y);
    __half h2 = __float2half_rn(v.z), h3 = __float2half_rn(v.w);
    __half l0 = __float2half_rn(v.x - __half2float(h0));
    __half l1 = __float2half_rn(v.y - __half2float(h1));
    __half l2 = __float2half_rn(v.z - __half2float(h2));
    __half l3 = __float2half_rn(v.w - __half2float(h3));
    hi.x = packh(h0, h1); hi.y = packh(h2, h3);
    lo.x = packh(l0, l1); lo.y = packh(l2, l3);
}

// centroid prep: fp16(2c) + exact |c|^2
__global__ void split_c_kernel(const float* __restrict__ c) {
    if (blockIdx.x == 0 && threadIdx.x == 0) g_fix_count = 0;  // reset per replay
    int w = (blockIdx.x * blockDim.x + threadIdx.x) >> 5;
    int lane = threadIdx.x & 31;
    const float4* r = (const float4*)(c + (size_t)w * DDIM);
    float4 a = r[lane], b = r[lane + 32];
    float s = a.x * a.x + a.y * a.y + a.z * a.z + a.w * a.w +
              b.x * b.x + b.y * b.y + b.z * b.z + b.w * b.w;
#pragma unroll
    for (int o = 16; o; o >>= 1) s += __shfl_xor_sync(0xffffffffu, s, o);
    if (lane == 0) g_cn[w] = s;
    uint2 hA, hB;
    {
        __half h0 = __float2half_rn(2.f * a.x), h1 = __float2half_rn(2.f * a.y);
        __half h2 = __float2half_rn(2.f * a.z), h3 = __float2half_rn(2.f * a.w);
        hA.x = packh(h0, h1); hA.y = packh(h2, h3);
        h0 = __float2half_rn(2.f * b.x); h1 = __float2half_rn(2.f * b.y);
        h2 = __float2half_rn(2.f * b.z); h3 = __float2half_rn(2.f * b.w);
        hB.x = packh(h0, h1); hB.y = packh(h2, h3);
    }
    uint2* ph = (uint2*)(g_ch + (size_t)w * DDIM);
    ph[lane] = hA; ph[lane + 32] = hB;
}

// ---------------- main HMMA kernel ----------------
// smem (dynamic, bytes):
//   XHI: 0       .. 73728   (4 d-chunks x [128 rows x 72 fp16], row stride 144B)
//   XLO: 73728   .. 147456
//   CBUF:147456  .. 202752  (3-slot ring, each slot = one C chunk, 18432B)
//   CN:  202752  .. 206848  (1024 f32)
//   XN:  206848  .. 207360  (128 f32 row norms)
#define XHI_OFF  0
#define XLO_OFF  73728
#define CBUF_OFF 147456
#define CN_OFF   202752
#define XN_OFF   206848
#define SMEM_SZ  207360
#define CHUNK_B  18432          /* 128*144 */
#define ROW_B    144

__global__ __launch_bounds__(256, 1) void assign_mma(
    const float* __restrict__ x, float* __restrict__ out, int Ntot) {
    extern __shared__ char smem[];
    const uint32_t sb = s2u(smem);
    const int tid = threadIdx.x;
    const int wid = tid >> 5;
    const int lane = tid & 31;
    const int warp_m = wid & 3;      // 0..3 -> 32-row slice
    const int warp_n = wid >> 2;     // 0..1 -> 64-col slice
    const int rowBase = blockIdx.x * 128;

    // per-lane ldmatrix offsets
    const int g8 = lane >> 3, r8 = lane & 7;
    const uint32_t offA = (uint32_t)((warp_m * 32 + r8 + (g8 & 1) * 8) * ROW_B + (g8 >> 1) * 16);
    const uint32_t offB = (uint32_t)((warp_n * 64 + r8 + (g8 >> 1) * 8) * ROW_B + (g8 & 1) * 16);

    // C staging map: 4 cp.async x 16B per thread per chunk
    const int crow = tid >> 3, cc8 = tid & 7;

    // stage chunk q (nt = q>>2, dc = q&3) into ring slot
    auto stageC = [&](int q, int slot) {
        const int nt = q >> 2, dc = q & 3;
        const char* gh = (const char*)(g_ch)
            + ((size_t)(nt * 128 + crow) * 256 + (size_t)dc * 64 + (size_t)cc8 * 8) * 2;
        uint32_t so = sb + CBUF_OFF + (uint32_t)(slot * CHUNK_B + crow * ROW_B + cc8 * 16);
#pragma unroll
        for (int i = 0; i < 4; i++)
            cp16(so + (uint32_t)(i * 32 * ROW_B), gh + (size_t)i * 32 * 512);
    };

    // ---- prologue: stage g0 (+cn) and g1 ----
    stageC(0, 0);
    cp16(sb + CN_OFF + (uint32_t)tid * 16, (const char*)g_cn + tid * 16);
    cp_commit();
    stageC(1, 1);
    cp_commit();

    if (tid < 128) *(float*)(smem + XN_OFF + tid * 4) = 0.f;
    __syncthreads();

    // in-register fp16 split of this CTA's X tile + row norms
    {
        const float4* gx = (const float4*)(x + (size_t)rowBase * DDIM);
        float* xnS = (float*)(smem + XN_OFF);
#pragma unroll
        for (int i = 0; i < 32; i++) {
            int idx = tid + i * 256;            // 0..8191
            int row = idx >> 6, c4 = idx & 63;  // 64 float4 per row
            float4 v = gx[(size_t)row * 64 + c4];
            uint2 hi, lo;
            split4h(v, hi, lo);
            uint32_t so = (uint32_t)((c4 >> 4) * CHUNK_B + row * ROW_B + (c4 & 15) * 8);
            *(uint2*)(smem + XHI_OFF + so) = hi;
            *(uint2*)(smem + XLO_OFF + so) = lo;
            float s = v.x * v.x + v.y * v.y + v.z * v.z + v.w * v.w;
#pragma unroll
            for (int o = 16; o; o >>= 1) s += __shfl_xor_sync(0xffffffffu, s, o);
            if (lane == 0) atomicAdd(&xnS[row], s);
        }
    }

    float acc[2][8][4];
#pragma unroll
    for (int mt = 0; mt < 2; mt++)
#pragma unroll
        for (int j = 0; j < 8; j++)
#pragma unroll
            for (int e = 0; e < 4; e++) acc[mt][j][e] = 0.f;

    float bestv[4], secv[4];
    int besti[4];
#pragma unroll
    for (int t = 0; t < 4; t++) { bestv[t] = -3.4e38f; secv[t] = -3.4e38f; besti[t] = 0; }

    const float* cnS = (const float*)(smem + CN_OFF);

    for (int q = 0; q < 32; q++) {
        const int nt = q >> 2, dc = q & 3;
        const int slot = q % 3;

        // gq must be complete (2 newer groups may remain in flight)
        cp_wait2();
        __syncthreads();

        // ---- compute on slot (B fragments double-buffered in regs) ----
        const uint32_t cbase = sb + CBUF_OFF + (uint32_t)(slot * CHUNK_B);
#pragma unroll
        for (int ks = 0; ks < 4; ks++) {
            uint32_t bh[2][4];
            ldsm4(bh[0], cbase + (uint32_t)(ks * 32) + offB);
            uint32_t ahi[2][4], alo[2][4];
            {
                uint32_t xb = sb + (uint32_t)(dc * CHUNK_B + ks * 32);
                ldsm4(ahi[0], xb + offA);
                ldsm4(ahi[1], xb + 2304 + offA);
                ldsm4(alo[0], xb + XLO_OFF + offA);
                ldsm4(alo[1], xb + XLO_OFF + 2304 + offA);
            }
#pragma unroll
            for (int nq = 0; nq < 4; nq++) {
                const int bc = nq & 1, bn = bc ^ 1;
                if (nq < 3)
                    ldsm4(bh[bn], cbase + (uint32_t)((nq + 1) * 2304 + ks * 32) + offB);
#pragma unroll
                for (int mt = 0; mt < 2; mt++) {
                    mma_f16(acc[mt][2 * nq],     ahi[mt], bh[bc]);
                    mma_f16(acc[mt][2 * nq],     alo[mt], bh[bc]);
                    mma_f16(acc[mt][2 * nq + 1], ahi[mt], bh[bc] + 2);
                    mma_f16(acc[mt][2 * nq + 1], alo[mt], bh[bc] + 2);
                }
            }
        }

        // ---- per-n-tile epilogue: fold cn, track top-2, clear accs ----
        if (dc == 3) {
#pragma unroll
            for (int mt = 0; mt < 2; mt++)
#pragma unroll
                for (int j = 0; j < 8; j++) {
                    int cg = nt * 128 + warp_n * 64 + j * 8 + (lane & 3) * 2;
                    float cn0 = cnS[cg], cn1 = cnS[cg + 1];
                    float* a = acc[mt][j];
                    float v0 = a[0] - cn0, v1 = a[1] - cn1;
                    float v2 = a[2] - cn0, v3 = a[3] - cn1;
                    int t0 = mt * 2, t1 = mt * 2 + 1;
                    if (v0 > bestv[t0]) { secv[t0] = bestv[t0]; bestv[t0] = v0; besti[t0] = cg; }
                    else if (v0 > secv[t0]) secv[t0] = v0;
                    if (v1 > bestv[t0]) { secv[t0] = bestv[t0]; bestv[t0] = v1; besti[t0] = cg + 1; }
                    else if (v1 > secv[t0]) secv[t0] = v1;
                    if (v2 > bestv[t1]) { secv[t1] = bestv[t1]; bestv[t1] = v2; besti[t1] = cg; }
                    else if (v2 > secv[t1]) secv[t1] = v2;
                    if (v3 > bestv[t1]) { secv[t1] = bestv[t1]; bestv[t1] = v3; besti[t1] = cg + 1; }
                    else if (v3 > secv[t1]) secv[t1] = v3;
                    a[0] = a[1] = a[2] = a[3] = 0.f;
                }
        }

        // ---- stage chunk q+2 (slot (q+2)%3, consumed-at-q-1 slot) ----
        if (q + 2 < 32) stageC(q + 2, (q + 2) % 3);
        cp_commit();   // empty group near tail keeps wait arithmetic uniform
    }
    cp_wait0();

    // ---- cross-lane top-2 reduce ----
#pragma unroll
    for (int off = 1; off < 4; off <<= 1) {
#pragma unroll
        for (int t = 0; t < 4; t++) {
            float ob = __shfl_xor_sync(0xffffffffu, bestv[t], off);
            float os = __shfl_xor_sync(0xffffffffu, secv[t], off);
            int oi = __shfl_xor_sync(0xffffffffu, besti[t], off);
            if (ob > bestv[t] || (ob == bestv[t] && oi < besti[t])) {
                secv[t] = fmaxf(bestv[t], os);
                bestv[t] = ob; besti[t] = oi;
            } else {
                secv[t] = fmaxf(secv[t], ob);
            }
        }
    }

    // ---- cross-warp (warp_n) reduce via smem ----
    __syncthreads();
    float* redB = (float*)(smem + CBUF_OFF);            // [2][128]
    float* redS = (float*)(smem + CBUF_OFF + 1024);     // [2][128]
    int*   redI = (int*)  (smem + CBUF_OFF + 2048);     // [2][128]
    if ((lane & 3) == 0) {
#pragma unroll
        for (int t = 0; t < 4; t++) {
            int row = warp_m * 32 + (t >> 1) * 16 + (lane >> 2) + (t & 1) * 8;
            redB[warp_n * 128 + row] = bestv[t];
            redS[warp_n * 128 + row] = secv[t];
            redI[warp_n * 128 + row] = besti[t];
        }
    }
    __syncthreads();
    if (tid < 128) {
        int row = tid;
        float b0 = redB[row], s0 = redS[row];
        int i0 = redI[row];
        float b1 = redB[128 + row], s1 = redS[128 + row];
        int i1 = redI[128 + row];
        float B, S; int I;
        if (b1 > b0 || (b1 == b0 && i1 < i0)) { B = b1; I = i1; S = fmaxf(b0, s1); }
        else                                  { B = b0; I = i0; S = fmaxf(s0, b1); }
        int g = rowBase + row;
        out[g] = B - *(const float*)(smem + XN_OFF + row * 4);
        out[Ntot + g] = (float)I;
        if (B - S < GAP_THR) {
            int p = atomicAdd(&g_fix_count, 1);
            if (p < FIXCAP) g_fix_list[p] = g;
        }
    }
}

// ---------------- exact fp32 fixup: 8 flagged rows per block ----------------
#define FIXROWS 8
__global__ __launch_bounds__(256) void fix_kernel(
    const float* __restrict__ x, const float* __restrict__ c,
    float* __restrict__ out, int Ntot) {
    int cnt = g_fix_count;
    if (cnt > FIXCAP) cnt = FIXCAP;
    int base = blockIdx.x * FIXROWS;
    if (base >= cnt) return;
    int nr = cnt - base; if (nr > FIXROWS) nr = FIXROWS;

    __shared__ float4 xs4[FIXROWS][64];
    __shared__ float xn[FIXROWS];
    __shared__ float wb[FIXROWS][8];
    __shared__ int   wi[FIXROWS][8];
    int t = threadIdx.x;
    int wid = t >> 5, lane = t & 31;

    // load rows (512 float4 total)
#pragma unroll
    for (int i = 0; i < 2; i++) {
        int idx = t + i * 256;
        int r = idx >> 6, d4 = idx & 63;
        if (r < nr) xs4[r][d4] = ((const float4*)(x + (size_t)g_fix_list[base + r] * DDIM))[d4];
    }
    __syncthreads();
    // row norms: warp w handles row w
    if (wid < nr) {
        float s = 0.f;
        for (int i = lane; i < 64; i += 32) {
            float4 a = xs4[wid][i];
            s += a.x * a.x + a.y * a.y + a.z * a.z + a.w * a.w;
        }
#pragma unroll
        for (int o = 16; o; o >>= 1) s += __shfl_xor_sync(0xffffffffu, s, o);
        if (lane == 0) xn[wid] = s;
    }
    __syncthreads();

    // each thread: 4 centroids x all rows
    float bestv[FIXROWS];
    int besti[FIXROWS];
#pragma unroll
    for (int r = 0; r < FIXROWS; r++) { bestv[r] = -3.4e38f; besti[r] = 0; }

#pragma unroll
    for (int j = 0; j < 4; j++) {
        int k = t + j * 256;
        const float4* cr = (const float4*)(c + (size_t)k * DDIM);
        float d[FIXROWS];
#pragma unroll
        for (int r = 0; r < FIXROWS; r++) d[r] = 0.f;
        for (int i = 0; i < 64; i++) {
            float4 b = cr[i];
#pragma unroll
            for (int r = 0; r < FIXROWS; r++) {
                float4 a = xs4[r][i];   // warp-uniform -> broadcast
                d[r] += a.x * b.x + a.y * b.y + a.z * b.z + a.w * b.w;
            }
        }
        float cn = g_cn[k];
#pragma unroll
        for (int r = 0; r < FIXROWS; r++) {
            float sim = 2.0f * d[r] - cn;
            if (sim > bestv[r] || (sim == bestv[r] && k < besti[r])) { bestv[r] = sim; besti[r] = k; }
        }
    }
    // warp reduce
#pragma unroll
    for (int off = 16; off; off >>= 1) {
#pragma unroll
        for (int r = 0; r < FIXROWS; r++) {
            float ov = __shfl_xor_sync(0xffffffffu, bestv[r], off);
            int oi = __shfl_xor_sync(0xffffffffu, besti[r], off);
            if (ov > bestv[r] || (ov == bestv[r] && oi < besti[r])) { bestv[r] = ov; besti[r] = oi; }
        }
    }
    if (lane == 0)
#pragma unroll
        for (int r = 0; r < FIXROWS; r++) { wb[r][wid] = bestv[r]; wi[r][wid] = besti[r]; }
    __syncthreads();
    if (t < nr) {
        float B = wb[t][0]; int I = wi[t][0];
#pragma unroll
        for (int w = 1; w < 8; w++) {
            float v = wb[t][w]; int i2 = wi[t][w];
            if (v > B || (v == B && i2 < I)) { B = v; I = i2; }
        }
        int row = g_fix_list[base + t];
        out[row] = B - xn[t];
        out[Ntot + row] = (float)I;
    }
}

// ---------------------------------------------------------------------------
extern "C" void kernel_launch(void* const* d_in, const int* in_sizes, int n_in,
                              void* d_out, int out_size) {
    const float* x = (const float*)d_in[0];
    const float* c = (const float*)d_in[1];
    float* out = (float*)d_out;

    const int D = 256;
    const int N = in_sizes[0] / D;   // 131072
    const int K = in_sizes[1] / D;   // 1024

    static int smem_set = 0;
    if (!smem_set) {
        cudaFuncSetAttribute((const void*)assign_mma,
                             cudaFuncAttributeMaxDynamicSharedMemorySize, SMEM_SZ);
        smem_set = 1;
    }

    split_c_kernel<<<K / 8, 256>>>(c);      // also resets g_fix_count
    assign_mma<<<N / 128, 256, SMEM_SZ>>>(x, out, N);
    fix_kernel<<<FIXCAP / FIXROWS, 256>>>(x, c, out, N);
}

// round 16
// speedup vs baseline: 3.9119x; 1.3282x over previous
#include <cuda_runtime.h>
#include <cuda_fp16.h>
#include <cstdint>

#define DEVINL __device__ __forceinline__

// ---------------- problem constants ----------------
#define NROWS 131072
#define KC    1024
#define DDIM  256
#define FIXCAP 8192
#define GAP_THR 0.05f

// ---------------- global scratch (allocation-free) ----------------
__device__ __align__(1024) __half g_ch[KC * DDIM];   // fp16(2c), single stream
__device__ float g_cn[KC];
__device__ int   g_fix_count;
__device__ int   g_fix_list[FIXCAP];

// ---------------- PTX helpers (sm_80-baseline only) ----------------
DEVINL uint32_t s2u(const void* p) {
    uint32_t a;
    asm("{ .reg .u64 t; cvta.to.shared.u64 t, %1; cvt.u32.u64 %0, t; }"
        : "=r"(a) : "l"(p));
    return a;
}
DEVINL void ldsm4(uint32_t* r, uint32_t addr) {
    asm volatile("ldmatrix.sync.aligned.m8n8.x4.shared.b16 {%0,%1,%2,%3}, [%4];"
                 : "=r"(r[0]), "=r"(r[1]), "=r"(r[2]), "=r"(r[3]) : "r"(addr));
}
DEVINL void mma_f16(float* d, const uint32_t* a, const uint32_t* b) {
    asm volatile(
        "mma.sync.aligned.m16n8k16.row.col.f32.f16.f16.f32 "
        "{%0,%1,%2,%3}, {%4,%5,%6,%7}, {%8,%9}, {%0,%1,%2,%3};"
        : "+f"(d[0]), "+f"(d[1]), "+f"(d[2]), "+f"(d[3])
        : "r"(a[0]), "r"(a[1]), "r"(a[2]), "r"(a[3]), "r"(b[0]), "r"(b[1]));
}
DEVINL void cp16(uint32_t saddr, const void* gaddr) {
    asm volatile("cp.async.cg.shared.global [%0], [%1], 16;"
                 :: "r"(saddr), "l"(gaddr) : "memory");
}
DEVINL void cp_commit() { asm volatile("cp.async.commit_group;" ::: "memory"); }
DEVINL void cp_wait2()  { asm volatile("cp.async.wait_group 2;"  ::: "memory"); }
DEVINL void cp_wait0()  { asm volatile("cp.async.wait_group 0;"  ::: "memory"); }

// ---------------- helpers ----------------
DEVINL uint32_t packh(__half a, __half b) {
    return (uint32_t)__half_as_ushort(a) | ((uint32_t)__half_as_ushort(b) << 16);
}

// centroid prep: fp16(2c) + exact |c|^2
__global__ void split_c_kernel(const float* __restrict__ c) {
    if (blockIdx.x == 0 && threadIdx.x == 0) g_fix_count = 0;  // reset per replay
    int w = (blockIdx.x * blockDim.x + threadIdx.x) >> 5;
    int lane = threadIdx.x & 31;
    const float4* r = (const float4*)(c + (size_t)w * DDIM);
    float4 a = r[lane], b = r[lane + 32];
    float s = a.x * a.x + a.y * a.y + a.z * a.z + a.w * a.w +
              b.x * b.x + b.y * b.y + b.z * b.z + b.w * b.w;
#pragma unroll
    for (int o = 16; o; o >>= 1) s += __shfl_xor_sync(0xffffffffu, s, o);
    if (lane == 0) g_cn[w] = s;
    uint2 hA, hB;
    {
        __half h0 = __float2half_rn(2.f * a.x), h1 = __float2half_rn(2.f * a.y);
        __half h2 = __float2half_rn(2.f * a.z), h3 = __float2half_rn(2.f * a.w);
        hA.x = packh(h0, h1); hA.y = packh(h2, h3);
        h0 = __float2half_rn(2.f * b.x); h1 = __float2half_rn(2.f * b.y);
        h2 = __float2half_rn(2.f * b.z); h3 = __float2half_rn(2.f * b.w);
        hB.x = packh(h0, h1); hB.y = packh(h2, h3);
    }
    uint2* ph = (uint2*)(g_ch + (size_t)w * DDIM);
    ph[lane] = hA; ph[lane + 32] = hB;
}

// ---------------- main HMMA kernel ----------------
// smem (dynamic, bytes):
//   XS:  0       .. 73728   (4 d-chunks x [128 rows x 72 fp16], row stride 144B)
//   CBUF:73728   .. 129024  (3-slot ring, each slot = one C chunk, 18432B)
//   CN:  129024  .. 133120  (1024 f32)
//   XN:  133120  .. 133632  (128 f32 row norms)
#define XS_OFF   0
#define CBUF_OFF 73728
#define CN_OFF   129024
#define XN_OFF   133120
#define SMEM_SZ  133632
#define CHUNK_B  18432          /* 128*144 */
#define ROW_B    144

__global__ __launch_bounds__(256, 1) void assign_mma(
    const float* __restrict__ x, float* __restrict__ out, int Ntot) {
    extern __shared__ char smem[];
    const uint32_t sb = s2u(smem);
    const int tid = threadIdx.x;
    const int wid = tid >> 5;
    const int lane = tid & 31;
    const int warp_m = wid & 3;      // 0..3 -> 32-row slice
    const int warp_n = wid >> 2;     // 0..1 -> 64-col slice
    const int rowBase = blockIdx.x * 128;

    // per-lane ldmatrix offsets
    const int g8 = lane >> 3, r8 = lane & 7;
    const uint32_t offA = (uint32_t)((warp_m * 32 + r8 + (g8 & 1) * 8) * ROW_B + (g8 >> 1) * 16);
    const uint32_t offB = (uint32_t)((warp_n * 64 + r8 + (g8 >> 1) * 8) * ROW_B + (g8 & 1) * 16);

    // C staging map: 4 cp.async x 16B per thread per chunk
    const int crow = tid >> 3, cc8 = tid & 7;

    auto stageC = [&](int q, int slot) {
        const int nt = q >> 2, dc = q & 3;
        const char* gh = (const char*)(g_ch)
            + ((size_t)(nt * 128 + crow) * 256 + (size_t)dc * 64 + (size_t)cc8 * 8) * 2;
        uint32_t so = sb + CBUF_OFF + (uint32_t)(slot * CHUNK_B + crow * ROW_B + cc8 * 16);
#pragma unroll
        for (int i = 0; i < 4; i++)
            cp16(so + (uint32_t)(i * 32 * ROW_B), gh + (size_t)i * 32 * 512);
    };

    // ---- prologue: stage q0 (+cn) and q1 ----
    stageC(0, 0);
    cp16(sb + CN_OFF + (uint32_t)tid * 16, (const char*)g_cn + tid * 16);
    cp_commit();
    stageC(1, 1);
    cp_commit();

    if (tid < 128) *(float*)(smem + XN_OFF + tid * 4) = 0.f;
    __syncthreads();

    // in-register fp16 round of this CTA's X tile + row norms
    {
        const float4* gx = (const float4*)(x + (size_t)rowBase * DDIM);
        float* xnS = (float*)(smem + XN_OFF);
#pragma unroll
        for (int i = 0; i < 32; i++) {
            int idx = tid + i * 256;            // 0..8191
            int row = idx >> 6, c4 = idx & 63;  // 64 float4 per row
            float4 v = gx[(size_t)row * 64 + c4];
            uint2 hi;
            hi.x = packh(__float2half_rn(v.x), __float2half_rn(v.y));
            hi.y = packh(__float2half_rn(v.z), __float2half_rn(v.w));
            uint32_t so = (uint32_t)((c4 >> 4) * CHUNK_B + row * ROW_B + (c4 & 15) * 8);
            *(uint2*)(smem + XS_OFF + so) = hi;
            float s = v.x * v.x + v.y * v.y + v.z * v.z + v.w * v.w;
#pragma unroll
            for (int o = 16; o; o >>= 1) s += __shfl_xor_sync(0xffffffffu, s, o);
            if (lane == 0) atomicAdd(&xnS[row], s);
        }
    }

    float acc[2][8][4];
#pragma unroll
    for (int mt = 0; mt < 2; mt++)
#pragma unroll
        for (int j = 0; j < 8; j++)
#pragma unroll
            for (int e = 0; e < 4; e++) acc[mt][j][e] = 0.f;

    float bestv[4], secv[4];
    int besti[4];
#pragma unroll
    for (int t = 0; t < 4; t++) { bestv[t] = -3.4e38f; secv[t] = -3.4e38f; besti[t] = 0; }

    const float* cnS = (const float*)(smem + CN_OFF);

    for (int q = 0; q < 32; q++) {
        const int nt = q >> 2, dc = q & 3;
        const int slot = q % 3;

        cp_wait2();
        __syncthreads();

        // ---- compute on slot (B fragments double-buffered in regs) ----
        const uint32_t cbase = sb + CBUF_OFF + (uint32_t)(slot * CHUNK_B);
#pragma unroll
        for (int ks = 0; ks < 4; ks++) {
            uint32_t bh[2][4];
            ldsm4(bh[0], cbase + (uint32_t)(ks * 32) + offB);
            uint32_t ah[2][4];
            {
                uint32_t xb = sb + (uint32_t)(dc * CHUNK_B + ks * 32);
                ldsm4(ah[0], xb + offA);
                ldsm4(ah[1], xb + 2304 + offA);
            }
#pragma unroll
            for (int nq = 0; nq < 4; nq++) {
                const int bc = nq & 1, bn = bc ^ 1;
                if (nq < 3)
                    ldsm4(bh[bn], cbase + (uint32_t)((nq + 1) * 2304 + ks * 32) + offB);
#pragma unroll
                for (int mt = 0; mt < 2; mt++) {
                    mma_f16(acc[mt][2 * nq],     ah[mt], bh[bc]);
                    mma_f16(acc[mt][2 * nq + 1], ah[mt], bh[bc] + 2);
                }
            }
        }

        // ---- per-n-tile epilogue: fold cn, track top-2, clear accs ----
        if (dc == 3) {
#pragma unroll
            for (int mt = 0; mt < 2; mt++)
#pragma unroll
                for (int j = 0; j < 8; j++) {
                    int cg = nt * 128 + warp_n * 64 + j * 8 + (lane & 3) * 2;
                    float cn0 = cnS[cg], cn1 = cnS[cg + 1];
                    float* a = acc[mt][j];
                    float v0 = a[0] - cn0, v1 = a[1] - cn1;
                    float v2 = a[2] - cn0, v3 = a[3] - cn1;
                    int t0 = mt * 2, t1 = mt * 2 + 1;
                    if (v0 > bestv[t0]) { secv[t0] = bestv[t0]; bestv[t0] = v0; besti[t0] = cg; }
                    else if (v0 > secv[t0]) secv[t0] = v0;
                    if (v1 > bestv[t0]) { secv[t0] = bestv[t0]; bestv[t0] = v1; besti[t0] = cg + 1; }
                    else if (v1 > secv[t0]) secv[t0] = v1;
                    if (v2 > bestv[t1]) { secv[t1] = bestv[t1]; bestv[t1] = v2; besti[t1] = cg; }
                    else if (v2 > secv[t1]) secv[t1] = v2;
                    if (v3 > bestv[t1]) { secv[t1] = bestv[t1]; bestv[t1] = v3; besti[t1] = cg + 1; }
                    else if (v3 > secv[t1]) secv[t1] = v3;
                    a[0] = a[1] = a[2] = a[3] = 0.f;
                }
        }

        // ---- stage chunk q+2 into slot (q+2)%3 ----
        if (q + 2 < 32) stageC(q + 2, (q + 2) % 3);
        cp_commit();   // empty group near tail keeps wait arithmetic uniform
    }
    cp_wait0();

    // ---- cross-lane top-2 reduce ----
#pragma unroll
    for (int off = 1; off < 4; off <<= 1) {
#pragma unroll
        for (int t = 0; t < 4; t++) {
            float ob = __shfl_xor_sync(0xffffffffu, bestv[t], off);
            float os = __shfl_xor_sync(0xffffffffu, secv[t], off);
            int oi = __shfl_xor_sync(0xffffffffu, besti[t], off);
            if (ob > bestv[t] || (ob == bestv[t] && oi < besti[t])) {
                secv[t] = fmaxf(bestv[t], os);
                bestv[t] = ob; besti[t] = oi;
            } else {
                secv[t] = fmaxf(secv[t], ob);
            }
        }
    }

    // ---- cross-warp (warp_n) reduce via smem ----
    __syncthreads();
    float* redB = (float*)(smem + CBUF_OFF);            // [2][128]
    float* redS = (float*)(smem + CBUF_OFF + 1024);     // [2][128]
    int*   redI = (int*)  (smem + CBUF_OFF + 2048);     // [2][128]
    if ((lane & 3) == 0) {
#pragma unroll
        for (int t = 0; t < 4; t++) {
            int row = warp_m * 32 + (t >> 1) * 16 + (lane >> 2) + (t & 1) * 8;
            redB[warp_n * 128 + row] = bestv[t];
            redS[warp_n * 128 + row] = secv[t];
            redI[warp_n * 128 + row] = besti[t];
        }
    }
    __syncthreads();
    if (tid < 128) {
        int row = tid;
        float b0 = redB[row], s0 = redS[row];
        int i0 = redI[row];
        float b1 = redB[128 + row], s1 = redS[128 + row];
        int i1 = redI[128 + row];
        float B, S; int I;
        if (b1 > b0 || (b1 == b0 && i1 < i0)) { B = b1; I = i1; S = fmaxf(b0, s1); }
        else                                  { B = b0; I = i0; S = fmaxf(s0, b1); }
        int g = rowBase + row;
        out[g] = B - *(const float*)(smem + XN_OFF + row * 4);
        out[Ntot + g] = (float)I;
        if (B - S < GAP_THR) {
            int p = atomicAdd(&g_fix_count, 1);
            if (p < FIXCAP) g_fix_list[p] = g;
        }
    }
}

// ---------------- exact fp32 fixup: 8 flagged rows per block ----------------
#define FIXROWS 8
__global__ __launch_bounds__(256) void fix_kernel(
    const float* __restrict__ x, const float* __restrict__ c,
    float* __restrict__ out, int Ntot) {
    int cnt = g_fix_count;
    if (cnt > FIXCAP) cnt = FIXCAP;
    int base = blockIdx.x * FIXROWS;
    if (base >= cnt) return;
    int nr = cnt - base; if (nr > FIXROWS) nr = FIXROWS;

    __shared__ float4 xs4[FIXROWS][64];
    __shared__ float xn[FIXROWS];
    __shared__ float wb[FIXROWS][8];
    __shared__ int   wi[FIXROWS][8];
    int t = threadIdx.x;
    int wid = t >> 5, lane = t & 31;

#pragma unroll
    for (int i = 0; i < 2; i++) {
        int idx = t + i * 256;
        int r = idx >> 6, d4 = idx & 63;
        if (r < nr) xs4[r][d4] = ((const float4*)(x + (size_t)g_fix_list[base + r] * DDIM))[d4];
    }
    __syncthreads();
    if (wid < nr) {
        float s = 0.f;
        for (int i = lane; i < 64; i += 32) {
            float4 a = xs4[wid][i];
            s += a.x * a.x + a.y * a.y + a.z * a.z + a.w * a.w;
        }
#pragma unroll
        for (int o = 16; o; o >>= 1) s += __shfl_xor_sync(0xffffffffu, s, o);
        if (lane == 0) xn[wid] = s;
    }
    __syncthreads();

    float bestv[FIXROWS];
    int besti[FIXROWS];
#pragma unroll
    for (int r = 0; r < FIXROWS; r++) { bestv[r] = -3.4e38f; besti[r] = 0; }

#pragma unroll
    for (int j = 0; j < 4; j++) {
        int k = t + j * 256;
        const float4* cr = (const float4*)(c + (size_t)k * DDIM);
        float d[FIXROWS];
#pragma unroll
        for (int r = 0; r < FIXROWS; r++) d[r] = 0.f;
        for (int i = 0; i < 64; i++) {
            float4 b = cr[i];
#pragma unroll
            for (int r = 0; r < FIXROWS; r++) {
                float4 a = xs4[r][i];   // warp-uniform -> broadcast
                d[r] += a.x * b.x + a.y * b.y + a.z * b.z + a.w * b.w;
            }
        }
        float cn = g_cn[k];
#pragma unroll
        for (int r = 0; r < FIXROWS; r++) {
            float sim = 2.0f * d[r] - cn;
            if (sim > bestv[r] || (sim == bestv[r] && k < besti[r])) { bestv[r] = sim; besti[r] = k; }
        }
    }
#pragma unroll
    for (int off = 16; off; off >>= 1) {
#pragma unroll
        for (int r = 0; r < FIXROWS; r++) {
            float ov = __shfl_xor_sync(0xffffffffu, bestv[r], off);
            int oi = __shfl_xor_sync(0xffffffffu, besti[r], off);
            if (ov > bestv[r] || (ov == bestv[r] && oi < besti[r])) { bestv[r] = ov; besti[r] = oi; }
        }
    }
    if (lane == 0)
#pragma unroll
        for (int r = 0; r < FIXROWS; r++) { wb[r][wid] = bestv[r]; wi[r][wid] = besti[r]; }
    __syncthreads();
    if (t < nr) {
        float B = wb[t][0]; int I = wi[t][0];
#pragma unroll
        for (int w = 1; w < 8; w++) {
            float v = wb[t][w]; int i2 = wi[t][w];
            if (v > B || (v == B && i2 < I)) { B = v; I = i2; }
        }
        int row = g_fix_list[base + t];
        out[row] = B - xn[t];
        out[Ntot + row] = (float)I;
    }
}

// ---------------------------------------------------------------------------
extern "C" void kernel_launch(void* const* d_in, const int* in_sizes, int n_in,
                              void* d_out, int out_size) {
    const float* x = (const float*)d_in[0];
    const float* c = (const float*)d_in[1];
    float* out = (float*)d_out;

    const int D = 256;
    const int N = in_sizes[0] / D;   // 131072
    const int K = in_sizes[1] / D;   // 1024

    static int smem_set = 0;
    if (!smem_set) {
        cudaFuncSetAttribute((const void*)assign_mma,
                             cudaFuncAttributeMaxDynamicSharedMemorySize, SMEM_SZ);
        smem_set = 1;
    }

    split_c_kernel<<<K / 8, 256>>>(c);      // also resets g_fix_count
    assign_mma<<<N / 128, 256, SMEM_SZ>>>(x, out, N);
    fix_kernel<<<FIXCAP / FIXROWS, 256>>>(x, c, out, N);
}

// round 17
// speedup vs baseline: 4.6595x; 1.1911x over previous
#include <cuda_runtime.h>
#include <cuda_fp16.h>
#include <cstdint>

#define DEVINL __device__ __forceinline__

// ---------------- problem constants ----------------
#define NROWS 131072
#define KC    1024
#define DDIM  256
#define FIXCAP 8192
#define GAP_THR 0.05f

// ---------------- global scratch (allocation-free) ----------------
__device__ __align__(1024) __half g_ch[KC * DDIM];   // fp16(2c), single stream
__device__ float g_cn[KC];
__device__ int   g_fix_count;
__device__ int   g_fix_list[FIXCAP];

// ---------------- PTX helpers (sm_80-baseline only) ----------------
DEVINL uint32_t s2u(const void* p) {
    uint32_t a;
    asm("{ .reg .u64 t; cvta.to.shared.u64 t, %1; cvt.u32.u64 %0, t; }"
        : "=r"(a) : "l"(p));
    return a;
}
DEVINL void ldsm4(uint32_t* r, uint32_t addr) {
    asm volatile("ldmatrix.sync.aligned.m8n8.x4.shared.b16 {%0,%1,%2,%3}, [%4];"
                 : "=r"(r[0]), "=r"(r[1]), "=r"(r[2]), "=r"(r[3]) : "r"(addr));
}
DEVINL void mma_f16(float* d, const uint32_t* a, const uint32_t* b) {
    asm volatile(
        "mma.sync.aligned.m16n8k16.row.col.f32.f16.f16.f32 "
        "{%0,%1,%2,%3}, {%4,%5,%6,%7}, {%8,%9}, {%0,%1,%2,%3};"
        : "+f"(d[0]), "+f"(d[1]), "+f"(d[2]), "+f"(d[3])
        : "r"(a[0]), "r"(a[1]), "r"(a[2]), "r"(a[3]), "r"(b[0]), "r"(b[1]));
}
DEVINL void cp16(uint32_t saddr, const void* gaddr) {
    asm volatile("cp.async.cg.shared.global [%0], [%1], 16;"
                 :: "r"(saddr), "l"(gaddr) : "memory");
}
DEVINL void cp_commit() { asm volatile("cp.async.commit_group;" ::: "memory"); }
DEVINL void cp_wait2()  { asm volatile("cp.async.wait_group 2;"  ::: "memory"); }
DEVINL void cp_wait0()  { asm volatile("cp.async.wait_group 0;"  ::: "memory"); }

// ---------------- helpers ----------------
DEVINL uint32_t packh(__half a, __half b) {
    return (uint32_t)__half_as_ushort(a) | ((uint32_t)__half_as_ushort(b) << 16);
}

// centroid prep: fp16(2c) + exact |c|^2
__global__ void split_c_kernel(const float* __restrict__ c) {
    if (blockIdx.x == 0 && threadIdx.x == 0) g_fix_count = 0;  // reset per replay
    int w = (blockIdx.x * blockDim.x + threadIdx.x) >> 5;
    int lane = threadIdx.x & 31;
    const float4* r = (const float4*)(c + (size_t)w * DDIM);
    float4 a = r[lane], b = r[lane + 32];
    float s = a.x * a.x + a.y * a.y + a.z * a.z + a.w * a.w +
              b.x * b.x + b.y * b.y + b.z * b.z + b.w * b.w;
#pragma unroll
    for (int o = 16; o; o >>= 1) s += __shfl_xor_sync(0xffffffffu, s, o);
    if (lane == 0) g_cn[w] = s;
    uint2 hA, hB;
    {
        __half h0 = __float2half_rn(2.f * a.x), h1 = __float2half_rn(2.f * a.y);
        __half h2 = __float2half_rn(2.f * a.z), h3 = __float2half_rn(2.f * a.w);
        hA.x = packh(h0, h1); hA.y = packh(h2, h3);
        h0 = __float2half_rn(2.f * b.x); h1 = __float2half_rn(2.f * b.y);
        h2 = __float2half_rn(2.f * b.z); h3 = __float2half_rn(2.f * b.w);
        hB.x = packh(h0, h1); hB.y = packh(h2, h3);
    }
    uint2* ph = (uint2*)(g_ch + (size_t)w * DDIM);
    ph[lane] = hA; ph[lane + 32] = hB;
}

// ---------------- main HMMA kernel: BM=64, 2 CTAs/SM ----------------
// smem (dynamic, bytes):
//   XS:  0      .. 36864   (4 d-chunks x [64 rows x 72 fp16], row stride 144B)
//   CBUF:36864  .. 92160   (3-slot ring, each slot = one C chunk = 128c x 64d, 18432B)
//   CN:  92160  .. 96256   (1024 f32)
//   XN:  96256  .. 96512   (64 f32 row norms)
#define XS_OFF    0
#define CBUF_OFF  36864
#define CN_OFF    92160
#define XN_OFF    96256
#define SMEM_SZ   96512
#define CHUNK_B   18432         /* C chunk: 128*144 */
#define CHUNK_XB  9216          /* X chunk: 64*144  */
#define ROW_B     144

__global__ __launch_bounds__(256, 2) void assign_mma(
    const float* __restrict__ x, float* __restrict__ out, int Ntot) {
    extern __shared__ char smem[];
    const uint32_t sb = s2u(smem);
    const int tid = threadIdx.x;
    const int wid = tid >> 5;
    const int lane = tid & 31;
    const int warp_m = wid & 1;      // 0..1 -> 32-row slice
    const int warp_n = wid >> 1;     // 0..3 -> 32-col slice
    const int rowBase = blockIdx.x * 64;

    // per-lane ldmatrix offsets
    const int g8 = lane >> 3, r8 = lane & 7;
    const uint32_t offA = (uint32_t)((warp_m * 32 + r8 + (g8 & 1) * 8) * ROW_B + (g8 >> 1) * 16);
    const uint32_t offB = (uint32_t)((warp_n * 32 + r8 + (g8 >> 1) * 8) * ROW_B + (g8 & 1) * 16);

    // C staging map: 4 cp.async x 16B per thread per chunk (128 cent-rows)
    const int crow = tid >> 3, cc8 = tid & 7;

    auto stageC = [&](int q, int slot) {
        const int nt = q >> 2, dc = q & 3;
        const char* gh = (const char*)(g_ch)
            + ((size_t)(nt * 128 + crow) * 256 + (size_t)dc * 64 + (size_t)cc8 * 8) * 2;
        uint32_t so = sb + CBUF_OFF + (uint32_t)(slot * CHUNK_B + crow * ROW_B + cc8 * 16);
#pragma unroll
        for (int i = 0; i < 4; i++)
            cp16(so + (uint32_t)(i * 32 * ROW_B), gh + (size_t)i * 32 * 512);
    };

    // ---- prologue: stage q0 (+cn) and q1 ----
    stageC(0, 0);
    cp16(sb + CN_OFF + (uint32_t)tid * 16, (const char*)g_cn + tid * 16);
    cp_commit();
    stageC(1, 1);
    cp_commit();

    if (tid < 64) *(float*)(smem + XN_OFF + tid * 4) = 0.f;
    __syncthreads();

    // in-register fp16 round of this CTA's X tile + row norms
    {
        const float4* gx = (const float4*)(x + (size_t)rowBase * DDIM);
        float* xnS = (float*)(smem + XN_OFF);
#pragma unroll
        for (int i = 0; i < 16; i++) {
            int idx = tid + i * 256;            // 0..4095
            int row = idx >> 6, c4 = idx & 63;  // 64 float4 per row
            float4 v = gx[(size_t)row * 64 + c4];
            uint2 hi;
            hi.x = packh(__float2half_rn(v.x), __float2half_rn(v.y));
            hi.y = packh(__float2half_rn(v.z), __float2half_rn(v.w));
            uint32_t so = (uint32_t)((c4 >> 4) * CHUNK_XB + row * ROW_B + (c4 & 15) * 8);
            *(uint2*)(smem + XS_OFF + so) = hi;
            float s = v.x * v.x + v.y * v.y + v.z * v.z + v.w * v.w;
#pragma unroll
            for (int o = 16; o; o >>= 1) s += __shfl_xor_sync(0xffffffffu, s, o);
            if (lane == 0) atomicAdd(&xnS[row], s);
        }
    }

    float acc[2][4][4];
#pragma unroll
    for (int mt = 0; mt < 2; mt++)
#pragma unroll
        for (int j = 0; j < 4; j++)
#pragma unroll
            for (int e = 0; e < 4; e++) acc[mt][j][e] = 0.f;

    float bestv[4], secv[4];
    int besti[4];
#pragma unroll
    for (int t = 0; t < 4; t++) { bestv[t] = -3.4e38f; secv[t] = -3.4e38f; besti[t] = 0; }

    const float* cnS = (const float*)(smem + CN_OFF);

    for (int q = 0; q < 32; q++) {
        const int nt = q >> 2, dc = q & 3;
        const int slot = q % 3;

        cp_wait2();
        __syncthreads();

        // ---- compute on slot ----
        const uint32_t cbase = sb + CBUF_OFF + (uint32_t)(slot * CHUNK_B) + offB;
        const uint32_t xb = sb + (uint32_t)(dc * CHUNK_XB) + offA;
#pragma unroll
        for (int ks = 0; ks < 4; ks++) {
            uint32_t bh[2][4], ah[2][4];
            ldsm4(bh[0], cbase + (uint32_t)(ks * 32));
            ldsm4(bh[1], cbase + (uint32_t)(2304 + ks * 32));
            ldsm4(ah[0], xb + (uint32_t)(ks * 32));
            ldsm4(ah[1], xb + (uint32_t)(2304 + ks * 32));
#pragma unroll
            for (int nq = 0; nq < 2; nq++)
#pragma unroll
                for (int mt = 0; mt < 2; mt++) {
                    mma_f16(acc[mt][2 * nq],     ah[mt], bh[nq]);
                    mma_f16(acc[mt][2 * nq + 1], ah[mt], bh[nq] + 2);
                }
        }

        // ---- per-n-tile epilogue: fold cn, track top-2, clear accs ----
        if (dc == 3) {
#pragma unroll
            for (int mt = 0; mt < 2; mt++)
#pragma unroll
                for (int j = 0; j < 4; j++) {
                    int cg = nt * 128 + warp_n * 32 + j * 8 + (lane & 3) * 2;
                    float cn0 = cnS[cg], cn1 = cnS[cg + 1];
                    float* a = acc[mt][j];
                    float v0 = a[0] - cn0, v1 = a[1] - cn1;
                    float v2 = a[2] - cn0, v3 = a[3] - cn1;
                    int t0 = mt * 2, t1 = mt * 2 + 1;
                    if (v0 > bestv[t0]) { secv[t0] = bestv[t0]; bestv[t0] = v0; besti[t0] = cg; }
                    else if (v0 > secv[t0]) secv[t0] = v0;
                    if (v1 > bestv[t0]) { secv[t0] = bestv[t0]; bestv[t0] = v1; besti[t0] = cg + 1; }
                    else if (v1 > secv[t0]) secv[t0] = v1;
                    if (v2 > bestv[t1]) { secv[t1] = bestv[t1]; bestv[t1] = v2; besti[t1] = cg; }
                    else if (v2 > secv[t1]) secv[t1] = v2;
                    if (v3 > bestv[t1]) { secv[t1] = bestv[t1]; bestv[t1] = v3; besti[t1] = cg + 1; }
                    else if (v3 > secv[t1]) secv[t1] = v3;
                    a[0] = a[1] = a[2] = a[3] = 0.f;
                }
        }

        // ---- stage chunk q+2 into slot (q+2)%3 ----
        if (q + 2 < 32) stageC(q + 2, (q + 2) % 3);
        cp_commit();   // empty group near tail keeps wait arithmetic uniform
    }
    cp_wait0();

    // ---- cross-lane top-2 reduce (lanes sharing a row differ in lane&3) ----
#pragma unroll
    for (int off = 1; off < 4; off <<= 1) {
#pragma unroll
        for (int t = 0; t < 4; t++) {
            float ob = __shfl_xor_sync(0xffffffffu, bestv[t], off);
            float os = __shfl_xor_sync(0xffffffffu, secv[t], off);
            int oi = __shfl_xor_sync(0xffffffffu, besti[t], off);
            if (ob > bestv[t] || (ob == bestv[t] && oi < besti[t])) {
                secv[t] = fmaxf(bestv[t], os);
                bestv[t] = ob; besti[t] = oi;
            } else {
                secv[t] = fmaxf(secv[t], ob);
            }
        }
    }

    // ---- cross-warp (warp_n: 4 groups) reduce via smem ----
    __syncthreads();
    float* redB = (float*)(smem + CBUF_OFF);            // [4][64]
    float* redS = (float*)(smem + CBUF_OFF + 1024);     // [4][64]
    int*   redI = (int*)  (smem + CBUF_OFF + 2048);     // [4][64]
    if ((lane & 3) == 0) {
#pragma unroll
        for (int t = 0; t < 4; t++) {
            int row = warp_m * 32 + (t >> 1) * 16 + (t & 1) * 8 + (lane >> 2);
            redB[warp_n * 64 + row] = bestv[t];
            redS[warp_n * 64 + row] = secv[t];
            redI[warp_n * 64 + row] = besti[t];
        }
    }
    __syncthreads();
    if (tid < 64) {
        int row = tid;
        float B = redB[row], S = redS[row];
        int I = redI[row];
#pragma unroll
        for (int g2 = 1; g2 < 4; g2++) {
            float b = redB[g2 * 64 + row], s = redS[g2 * 64 + row];
            int i2 = redI[g2 * 64 + row];
            if (b > B || (b == B && i2 < I)) { S = fmaxf(B, s); B = b; I = i2; }
            else                              { S = fmaxf(S, b); }
        }
        int g = rowBase + row;
        out[g] = B - *(const float*)(smem + XN_OFF + row * 4);
        out[Ntot + g] = (float)I;
        if (B - S < GAP_THR) {
            int p = atomicAdd(&g_fix_count, 1);
            if (p < FIXCAP) g_fix_list[p] = g;
        }
    }
}

// ---------------- exact fp32 fixup: 8 flagged rows per block ----------------
#define FIXROWS 8
__global__ __launch_bounds__(256) void fix_kernel(
    const float* __restrict__ x, const float* __restrict__ c,
    float* __restrict__ out, int Ntot) {
    int cnt = g_fix_count;
    if (cnt > FIXCAP) cnt = FIXCAP;
    int base = blockIdx.x * FIXROWS;
    if (base >= cnt) return;
    int nr = cnt - base; if (nr > FIXROWS) nr = FIXROWS;

    __shared__ float4 xs4[FIXROWS][64];
    __shared__ float xn[FIXROWS];
    __shared__ float wb[FIXROWS][8];
    __shared__ int   wi[FIXROWS][8];
    int t = threadIdx.x;
    int wid = t >> 5, lane = t & 31;

#pragma unroll
    for (int i = 0; i < 2; i++) {
        int idx = t + i * 256;
        int r = idx >> 6, d4 = idx & 63;
        if (r < nr) xs4[r][d4] = ((const float4*)(x + (size_t)g_fix_list[base + r] * DDIM))[d4];
    }
    __syncthreads();
    if (wid < nr) {
        float s = 0.f;
        for (int i = lane; i < 64; i += 32) {
            float4 a = xs4[wid][i];
            s += a.x * a.x + a.y * a.y + a.z * a.z + a.w * a.w;
        }
#pragma unroll
        for (int o = 16; o; o >>= 1) s += __shfl_xor_sync(0xffffffffu, s, o);
        if (lane == 0) xn[wid] = s;
    }
    __syncthreads();

    float bestv[FIXROWS];
    int besti[FIXROWS];
#pragma unroll
    for (int r = 0; r < FIXROWS; r++) { bestv[r] = -3.4e38f; besti[r] = 0; }

#pragma unroll
    for (int j = 0; j < 4; j++) {
        int k = t + j * 256;
        const float4* cr = (const float4*)(c + (size_t)k * DDIM);
        float d[FIXROWS];
#pragma unroll
        for (int r = 0; r < FIXROWS; r++) d[r] = 0.f;
        for (int i = 0; i < 64; i++) {
            float4 b = cr[i];
#pragma unroll
            for (int r = 0; r < FIXROWS; r++) {
                float4 a = xs4[r][i];   // warp-uniform -> broadcast
                d[r] += a.x * b.x + a.y * b.y + a.z * b.z + a.w * b.w;
            }
        }
        float cn = g_cn[k];
#pragma unroll
        for (int r = 0; r < FIXROWS; r++) {
            float sim = 2.0f * d[r] - cn;
            if (sim > bestv[r] || (sim == bestv[r] && k < besti[r])) { bestv[r] = sim; besti[r] = k; }
        }
    }
#pragma unroll
    for (int off = 16; off; off >>= 1) {
#pragma unroll
        for (int r = 0; r < FIXROWS; r++) {
            float ov = __shfl_xor_sync(0xffffffffu, bestv[r], off);
            int oi = __shfl_xor_sync(0xffffffffu, besti[r], off);
            if (ov > bestv[r] || (ov == bestv[r] && oi < besti[r])) { bestv[r] = ov; besti[r] = oi; }
        }
    }
    if (lane == 0)
#pragma unroll
        for (int r = 0; r < FIXROWS; r++) { wb[r][wid] = bestv[r]; wi[r][wid] = besti[r]; }
    __syncthreads();
    if (t < nr) {
        float B = wb[t][0]; int I = wi[t][0];
#pragma unroll
        for (int w = 1; w < 8; w++) {
            float v = wb[t][w]; int i2 = wi[t][w];
            if (v > B || (v == B && i2 < I)) { B = v; I = i2; }
        }
        int row = g_fix_list[base + t];
        out[row] = B - xn[t];
        out[Ntot + row] = (float)I;
    }
}

// ---------------------------------------------------------------------------
extern "C" void kernel_launch(void* const* d_in, const int* in_sizes, int n_in,
                              void* d_out, int out_size) {
    const float* x = (const float*)d_in[0];
    const float* c = (const float*)d_in[1];
    float* out = (float*)d_out;

    const int D = 256;
    const int N = in_sizes[0] / D;   // 131072
    const int K = in_sizes[1] / D;   // 1024

    static int smem_set = 0;
    if (!smem_set) {
        cudaFuncSetAttribute((const void*)assign_mma,
                             cudaFuncAttributeMaxDynamicSharedMemorySize, SMEM_SZ);
        smem_set = 1;
    }

    split_c_kernel<<<K / 8, 256>>>(c);      // also resets g_fix_count
    assign_mma<<<N / 64, 256, SMEM_SZ>>>(x, out, N);
    fix_kernel<<<FIXCAP / FIXROWS, 256>>>(x, c, out, N);
}